// round 9
// baseline (speedup 1.0000x reference)
#include <cuda_runtime.h>
#include <cuda_bf16.h>
#include <cstdint>

#define SLEN  512
#define BATCH 64
#define HID   512
#define NCTA  64
#define NTHR  256
#define AB    272                   // smem row pitch bytes (136 bf16): conflict-free ldmatrix
#define A_BUF (128 * AB)            // 34816: A chunk (128 rows x 128 k)
#define B_BUF (64 * AB)             // 17408: B chunk (64 n' x 128 k)
#define SM_A0 0                     // 2 x A_BUF (phase A input tile)
#define SM_A1 (2 * A_BUF)           // 2 x A_BUF (phase B input tile)
#define SM_B0 (4 * A_BUF)           // 2 x B_BUF (phase A weights)
#define SM_B1 (4 * A_BUF + 2 * B_BUF)
#define SM_X  (4 * A_BUF + 4 * B_BUF)        // xchg: 64 x 33 floats
#define SM_TOTAL (SM_X + 64 * 33 * 4)        // 217344 B

typedef __nv_bfloat16 bf16;

// ---- persistent device state (allocation-free rule) ----
__device__ __align__(128) bf16  gx[SLEN][128][HID];   // x split: rows 0-63 hi, 64-127 lo
__device__ __align__(128) bf16  gh0s[2][128][HID];    // h0 split, ping-pong
__device__ __align__(128) bf16  gh1s[2][128][HID];    // h1 split, ping-pong
__device__ __align__(128) float g_c0[BATCH * HID];
__device__ __align__(128) float g_c1[BATCH * HID];
// weights: [layer][cta][n'(64)][k(1024)]; n'<32 = hi, n'>=32 = lo of col(n'-32)
// col(n) for n=gg*16+idx16: g=(idx16&1)*2+(idx16>>3), q=(idx16>>1)&3 -> g*512 + cta*8 + gg*4 + q
__device__ __align__(128) bf16  g_wb[2][NCTA][64][1024];

// ---------------- helpers ----------------
__device__ __forceinline__ uint32_t smem_u32(const void* p) {
    uint32_t a;
    asm("{ .reg .u64 t; cvta.to.shared.u64 t, %1; cvt.u32.u64 %0, t; }" : "=r"(a) : "l"(p));
    return a;
}
__device__ __forceinline__ void cpa16(uint32_t dst, const void* src) {
    asm volatile("cp.async.cg.shared.global [%0], [%1], 16;\n" :: "r"(dst), "l"(src));
}
__device__ __forceinline__ void cp_commit() { asm volatile("cp.async.commit_group;\n" ::: "memory"); }
__device__ __forceinline__ void cp_wait1()  { asm volatile("cp.async.wait_group 1;\n" ::: "memory"); }
__device__ __forceinline__ void cp_wait0()  { asm volatile("cp.async.wait_group 0;\n" ::: "memory"); }

__device__ __forceinline__ void ldsm4(uint32_t& r0, uint32_t& r1, uint32_t& r2, uint32_t& r3,
                                      uint32_t addr) {
    asm volatile("ldmatrix.sync.aligned.m8n8.x4.shared.b16 {%0,%1,%2,%3}, [%4];"
                 : "=r"(r0), "=r"(r1), "=r"(r2), "=r"(r3) : "r"(addr));
}
__device__ __forceinline__ void mma16816(float* d, const uint32_t* a, uint32_t b0, uint32_t b1) {
    asm volatile(
        "mma.sync.aligned.m16n8k16.row.col.f32.bf16.bf16.f32 "
        "{%0,%1,%2,%3}, {%4,%5,%6,%7}, {%8,%9}, {%0,%1,%2,%3};"
        : "+f"(d[0]), "+f"(d[1]), "+f"(d[2]), "+f"(d[3])
        : "r"(a[0]), "r"(a[1]), "r"(a[2]), "r"(a[3]), "r"(b0), "r"(b1));
}
__device__ __forceinline__ float sigf(float x) { return 1.0f / (1.0f + __expf(-x)); }

// ---- stage A chunk (128 rows x 128 k) / B chunk (64 n' x 128 k) ----
__device__ __forceinline__ void stageA(uint32_t ab, const bf16* __restrict__ a, int tid) {
#pragma unroll
    for (int i = 0; i < 8; i++) {
        int u = i * NTHR + tid;            // 0..2047
        int row = u >> 4, cu = u & 15;
        cpa16(ab + row * AB + cu * 16, a + row * HID + cu * 8);
    }
}
__device__ __forceinline__ void stageB(uint32_t bb, const bf16* __restrict__ b, int tid) {
#pragma unroll
    for (int i = 0; i < 4; i++) {
        int u = i * NTHR + tid;            // 0..1023
        int row = u >> 4, cu = u & 15;
        cpa16(bb + row * AB + cu * 16, b + row * 1024 + cu * 8);
    }
}

// ---- one chunk, one phase: warp w rows 16w..16w+15, all 64 n' -> 32 acc ----
__device__ __forceinline__ void mma_chunk(uint32_t aBase, uint32_t bBase, int w, int l,
                                          float* __restrict__ d) {
    uint32_t sA = aBase + (16 * w + (l & 15)) * AB + (l >> 4) * 16;
    uint32_t sB = bBase + (l & 15) * AB + (l >> 4) * 16;
#pragma unroll
    for (int j = 0; j < 8; j++) {          // 8 k-steps of 16
        uint32_t a[4];
        ldsm4(a[0], a[1], a[2], a[3], sA + j * 32);
#pragma unroll
        for (int g = 0; g < 4; g++) {      // n' rows 16g..16g+15 -> tiles 2g, 2g+1
            uint32_t p0, p1, p2, p3;
            ldsm4(p0, p1, p2, p3, sB + g * 16 * AB + j * 32);
            mma16816(d + (2 * g) * 4,     a, p0, p2);
            mma16816(d + (2 * g + 1) * 4, a, p1, p3);
        }
    }
}

// ---- epilogue: fold cols (n', n'+32) locally, rows (r, r+64) via smem ----
__device__ void epilogue(const float* __restrict__ d, float* __restrict__ xchg,
                         const float* __restrict__ bias, float* __restrict__ cst,
                         bf16* __restrict__ hdst, float* __restrict__ odst,
                         int cta, int w, int l) {
    float ff[2][2][4];                     // [group][t][reg]: hi+lo col fold
#pragma unroll
    for (int gg = 0; gg < 2; gg++)
#pragma unroll
        for (int t = 0; t < 2; t++)
#pragma unroll
            for (int r = 0; r < 4; r++)
                ff[gg][t][r] = d[(gg * 2 + t) * 4 + r] + d[(gg * 2 + t + 4) * 4 + r];

    const int q = l & 3;
    const int row0 = 16 * w + (l >> 2);
    if (w >= 4) {                          // rows 64-127 = lo partials -> xchg
#pragma unroll
        for (int rr = 0; rr < 2; rr++) {
            int row = row0 + rr * 8 - 64;
#pragma unroll
            for (int gg = 0; gg < 2; gg++)
#pragma unroll
                for (int t = 0; t < 2; t++)
#pragma unroll
                    for (int j = 0; j < 2; j++)
                        xchg[row * 33 + gg * 16 + (j * 2 + t) * 4 + q] = ff[gg][t][rr * 2 + j];
        }
    }
    __syncthreads();
    if (w < 4) {                           // rows 0-63: full result
#pragma unroll
        for (int gg = 0; gg < 2; gg++) {
            const int hc = cta * 8 + gg * 4 + q;
            float b2f  = 2.f * bias[hc];
            float b2i1 = 2.f * bias[HID + hc];
            float b2i2 = 2.f * bias[2 * HID + hc];
            float b2o  = 2.f * bias[3 * HID + hc];
#pragma unroll
            for (int rr = 0; rr < 2; rr++) {
                int row = row0 + rr * 8;
                const float* xr = xchg + row * 33 + gg * 16;
                float gf = ff[gg][0][rr * 2 + 0] + xr[0 * 4 + q] + b2f;
                float g1 = ff[gg][1][rr * 2 + 0] + xr[1 * 4 + q] + b2i1;
                float g2 = ff[gg][0][rr * 2 + 1] + xr[2 * 4 + q] + b2i2;
                float go = ff[gg][1][rr * 2 + 1] + xr[3 * 4 + q] + b2o;
                float c = cst[row * HID + hc];
                c = sigf(gf) * c + sigf(g1) * tanhf(g2);
                cst[row * HID + hc] = c;
                float h = sigf(go) * tanhf(c);
                bf16 hi = __float2bfloat16(h);
                bf16 lo = __float2bfloat16(h - __bfloat162float(hi));
                hdst[row * HID + hc] = hi;
                hdst[(row + 64) * HID + hc] = lo;
                if (odst) odst[row * HID + hc] = h;
            }
        }
    }
    __syncthreads();                       // xchg reuse safety
}

// ---- one-time per replay: split x into bf16 hi/lo stacked rows ----
__global__ void pack_x(const float* __restrict__ x) {
    size_t i = (size_t)blockIdx.x * blockDim.x + threadIdx.x;
    if (i < (size_t)SLEN * BATCH * HID) {
        int kk = (int)(i % HID);
        size_t sr = i / HID;
        int r = (int)(sr % BATCH);
        int s = (int)(sr / BATCH);
        float v = x[i];
        bf16 hi = __float2bfloat16(v);
        gx[s][r][kk] = hi;
        gx[s][64 + r][kk] = __float2bfloat16(v - __bfloat162float(hi));
    }
}

// ---- one-time per replay: split + permute weights ----
__global__ void pack_w(const float* __restrict__ Wx0, const float* __restrict__ Wh0,
                       const float* __restrict__ Wx1, const float* __restrict__ Wh1) {
    size_t i = (size_t)blockIdx.x * blockDim.x + threadIdx.x;  // 2*64*64*1024
    if (i >= (size_t)2 * NCTA * 64 * 1024) return;
    int kk = (int)(i & 1023);
    size_t t = i >> 10;
    int n64 = (int)(t & 63); t >>= 6;
    int cta = (int)(t & 63);
    int layer = (int)(t >> 6);
    int idx = n64 & 31;
    int gg = idx >> 4;
    int idx16 = idx & 15;
    int g = (idx16 & 1) * 2 + (idx16 >> 3);
    int q = (idx16 >> 1) & 3;
    int col = g * HID + cta * 8 + gg * 4 + q;
    const float* Wx = layer ? Wx1 : Wx0;
    const float* Wh = layer ? Wh1 : Wh0;
    float v = (kk < HID) ? Wx[kk * 2048 + col] : Wh[(kk - HID) * 2048 + col];
    bf16 hi = __float2bfloat16(v);
    g_wb[layer][cta][n64][kk] = (n64 < 32) ? hi
                              : __float2bfloat16(v - __bfloat162float(hi));
}

__global__ void init_kernel() {
    int idx = blockIdx.x * blockDim.x + threadIdx.x;
    if (idx < 2 * 128 * HID) {
        ((bf16*)gh0s)[idx] = __float2bfloat16(0.f);
        ((bf16*)gh1s)[idx] = __float2bfloat16(0.f);
    }
    if (idx < BATCH * HID) { g_c0[idx] = 0.f; g_c1[idx] = 0.f; }
}

// ---- skewed step, MERGED phases: launch k runs layer0(step k) and layer1(step k-1)
// concurrently (they are independent: B reads only previous-launch state). ----
__global__ __launch_bounds__(NTHR, 1)
void step_kernel(const float* __restrict__ b0, const float* __restrict__ b1,
                 float* __restrict__ out, int k) {
    extern __shared__ char smem[];
    uint32_t sb = smem_u32(smem);
    float* xchg = (float*)(smem + SM_X);
    const int tid = threadIdx.x, w = tid >> 5, l = tid & 31;
    const int cta = blockIdx.x;
    const int p = k & 1, pq = p ^ 1;
    const bool doA = (k < SLEN), doB = (k > 0);

    float dA[32], dB[32];
#pragma unroll
    for (int j = 0; j < 32; j++) { dA[j] = 0.f; dB[j] = 0.f; }

    // chunk c: k-range [c*128, c*128+128); c<4 -> first source, c>=4 -> second
    auto stage_iter = [&](int c, int buf) {
        if (doA) {
            const bf16* aA = (c < 4) ? (&gx[k][0][0] + c * 128)
                                     : (&gh0s[p][0][0] + (c - 4) * 128);
            stageA(sb + SM_A0 + buf * A_BUF, aA, tid);
            stageB(sb + SM_B0 + buf * B_BUF, &g_wb[0][cta][0][0] + c * 128, tid);
        }
        if (doB) {
            const bf16* aB = (c < 4) ? (&gh0s[p][0][0] + c * 128)
                                     : (&gh1s[p][0][0] + (c - 4) * 128);
            stageA(sb + SM_A1 + buf * A_BUF, aB, tid);
            stageB(sb + SM_B1 + buf * B_BUF, &g_wb[1][cta][0][0] + c * 128, tid);
        }
        cp_commit();
    };

    stage_iter(0, 0);
#pragma unroll 1
    for (int c = 0; c < 8; c++) {
        if (c < 7) {
            stage_iter(c + 1, (c + 1) & 1);
            cp_wait1();                    // chunk c landed
        } else {
            cp_wait0();
        }
        __syncthreads();
        if (doA) mma_chunk(sb + SM_A0 + (c & 1) * A_BUF, sb + SM_B0 + (c & 1) * B_BUF, w, l, dA);
        if (doB) mma_chunk(sb + SM_A1 + (c & 1) * A_BUF, sb + SM_B1 + (c & 1) * B_BUF, w, l, dB);
        __syncthreads();
    }

    if (doA) epilogue(dA, xchg, b0, g_c0, &gh0s[pq][0][0], nullptr, cta, w, l);
    if (doB) epilogue(dB, xchg, b1, g_c1, &gh1s[pq][0][0],
                      out + (size_t)(k - 1) * BATCH * HID, cta, w, l);
}

extern "C" void kernel_launch(void* const* d_in, const int* in_sizes, int n_in,
                              void* d_out, int out_size) {
    const float* x   = (const float*)d_in[0];
    const float* Wx0 = (const float*)d_in[1];
    const float* Wh0 = (const float*)d_in[2];
    const float* b0  = (const float*)d_in[3];
    const float* Wx1 = (const float*)d_in[4];
    const float* Wh1 = (const float*)d_in[5];
    const float* b1  = (const float*)d_in[6];
    float* out = (float*)d_out;

    static int attr_done = 0;
    if (!attr_done) {
        cudaFuncSetAttribute(step_kernel,
                             cudaFuncAttributeMaxDynamicSharedMemorySize, SM_TOTAL);
        attr_done = 1;
    }

    pack_x<<<(SLEN * BATCH * HID + 255) / 256, 256>>>(x);
    pack_w<<<(int)((2ull * NCTA * 64 * 1024 + 255) / 256), 256>>>(Wx0, Wh0, Wx1, Wh1);
    init_kernel<<<(2 * 128 * HID + 255) / 256, 256>>>();
    for (int k = 0; k <= SLEN; k++) {
        step_kernel<<<NCTA, NTHR, SM_TOTAL>>>(b0, b1, out, k);
    }
}

// round 10
// speedup vs baseline: 1.3636x; 1.3636x over previous
#include <cuda_runtime.h>
#include <cuda_bf16.h>
#include <cstdint>

#define SLEN  512
#define BATCH 64
#define HID   512
#define NCTA  128
#define NTHR  256
#define AB    272                   // smem row pitch bytes: conflict-free ldmatrix
#define A_BUF (128 * AB)            // 34816: A chunk (128 rows x 128 k)
#define B_BUF (32 * AB)             // 8704:  B chunk (32 n' x 128 k)
#define SM_A0 0                     // 2 x A_BUF (phase A input tile)
#define SM_A1 (2 * A_BUF)           // 2 x A_BUF (phase B input tile)
#define SM_B0 (4 * A_BUF)           // 2 x B_BUF (phase A weights)
#define SM_B1 (4 * A_BUF + 2 * B_BUF)
#define SM_X  (4 * A_BUF + 4 * B_BUF)      // xchg: 64 x 17 floats
#define SM_TOTAL (SM_X + 64 * 17 * 4)      // 178432 B

typedef __nv_bfloat16 bf16;

// ---- persistent device state (allocation-free rule) ----
__device__ __align__(128) bf16  gx[SLEN][128][HID];   // x split: rows 0-63 hi, 64-127 lo
__device__ __align__(128) bf16  gh0s[2][128][HID];    // h0 split, ping-pong
__device__ __align__(128) bf16  gh1s[2][128][HID];    // h1 split, ping-pong
__device__ __align__(128) float g_c0[BATCH * HID];
__device__ __align__(128) float g_c1[BATCH * HID];
// weights: [layer][cta][n'(32)][k(1024)]; n'<16 = hi, n'>=16 = lo of col(n'-16)
// col(n) = g*512 + cta*4 + q, with g = (n&1)*2 + (n>>3), q = (n>>1)&3
__device__ __align__(128) bf16  g_wb[2][NCTA][32][1024];

// ---------------- helpers ----------------
__device__ __forceinline__ uint32_t smem_u32(const void* p) {
    uint32_t a;
    asm("{ .reg .u64 t; cvta.to.shared.u64 t, %1; cvt.u32.u64 %0, t; }" : "=r"(a) : "l"(p));
    return a;
}
__device__ __forceinline__ void cpa16(uint32_t dst, const void* src) {
    asm volatile("cp.async.cg.shared.global [%0], [%1], 16;\n" :: "r"(dst), "l"(src));
}
__device__ __forceinline__ void cp_commit() { asm volatile("cp.async.commit_group;\n" ::: "memory"); }
__device__ __forceinline__ void cp_wait1()  { asm volatile("cp.async.wait_group 1;\n" ::: "memory"); }
__device__ __forceinline__ void cp_wait0()  { asm volatile("cp.async.wait_group 0;\n" ::: "memory"); }

__device__ __forceinline__ void ldsm4(uint32_t& r0, uint32_t& r1, uint32_t& r2, uint32_t& r3,
                                      uint32_t addr) {
    asm volatile("ldmatrix.sync.aligned.m8n8.x4.shared.b16 {%0,%1,%2,%3}, [%4];"
                 : "=r"(r0), "=r"(r1), "=r"(r2), "=r"(r3) : "r"(addr));
}
__device__ __forceinline__ void mma16816(float* d, const uint32_t* a, uint32_t b0, uint32_t b1) {
    asm volatile(
        "mma.sync.aligned.m16n8k16.row.col.f32.bf16.bf16.f32 "
        "{%0,%1,%2,%3}, {%4,%5,%6,%7}, {%8,%9}, {%0,%1,%2,%3};"
        : "+f"(d[0]), "+f"(d[1]), "+f"(d[2]), "+f"(d[3])
        : "r"(a[0]), "r"(a[1]), "r"(a[2]), "r"(a[3]), "r"(b0), "r"(b1));
}
__device__ __forceinline__ float sigf(float x) { return 1.0f / (1.0f + __expf(-x)); }

// ---- stage A chunk (128 rows x 128 k) / B chunk (32 n' x 128 k) ----
__device__ __forceinline__ void stageA(uint32_t ab, const bf16* __restrict__ a, int tid) {
#pragma unroll
    for (int i = 0; i < 8; i++) {
        int u = i * NTHR + tid;            // 0..2047
        int row = u >> 4, cu = u & 15;
        cpa16(ab + row * AB + cu * 16, a + row * HID + cu * 8);
    }
}
__device__ __forceinline__ void stageB(uint32_t bb, const bf16* __restrict__ b, int tid) {
#pragma unroll
    for (int i = 0; i < 2; i++) {
        int u = i * NTHR + tid;            // 0..511
        int row = u >> 4, cu = u & 15;
        cpa16(bb + row * AB + cu * 16, b + row * 1024 + cu * 8);
    }
}

// ---- one chunk, one phase: warp w rows 16w..16w+15, all 32 n' -> 16 acc ----
__device__ __forceinline__ void mma_chunk(uint32_t aBase, uint32_t bBase, int w, int l,
                                          float* __restrict__ d) {
    uint32_t sA  = aBase + (16 * w + (l & 15)) * AB + (l >> 4) * 16;
    uint32_t sB0 = bBase + (l & 15) * AB + (l >> 4) * 16;
    uint32_t sB1 = sB0 + 16 * AB;
#pragma unroll
    for (int j = 0; j < 8; j++) {          // 8 k-steps of 16
        uint32_t a[4], p0, p1, p2, p3, q0, q1, q2, q3;
        ldsm4(a[0], a[1], a[2], a[3], sA + j * 32);
        ldsm4(p0, p1, p2, p3, sB0 + j * 32);   // n' 0-15 (hi cols)
        ldsm4(q0, q1, q2, q3, sB1 + j * 32);   // n' 16-31 (lo cols)
        mma16816(d + 0,  a, p0, p2);       // tile0: n 0-7 hi
        mma16816(d + 4,  a, p1, p3);       // tile1: n 8-15 hi
        mma16816(d + 8,  a, q0, q2);       // tile2: lo of tile0
        mma16816(d + 12, a, q1, q3);       // tile3: lo of tile1
    }
}

// ---- epilogue: fold cols (n, n+16) locally, rows (r, r+64) via smem ----
__device__ void epilogue(const float* __restrict__ d, float* __restrict__ xchg,
                         const float* __restrict__ bias, float* __restrict__ cst,
                         bf16* __restrict__ hdst, float* __restrict__ odst,
                         int cta, int w, int l) {
    float ff[2][4];                        // [t][reg]: hi+lo col fold
#pragma unroll
    for (int t = 0; t < 2; t++)
#pragma unroll
        for (int r = 0; r < 4; r++) ff[t][r] = d[t * 4 + r] + d[(t + 2) * 4 + r];

    const int q = l & 3;
    const int row0 = 16 * w + (l >> 2);
    // gate of (t, j) = j*2 + t:  t0j0=f, t1j0=i1, t0j1=i2, t1j1=o
    if (w >= 4) {                          // rows 64-127 = lo partials -> xchg
#pragma unroll
        for (int rr = 0; rr < 2; rr++) {
            int row = row0 + rr * 8 - 64;
#pragma unroll
            for (int t = 0; t < 2; t++)
#pragma unroll
                for (int j = 0; j < 2; j++)
                    xchg[row * 17 + (j * 2 + t) * 4 + q] = ff[t][rr * 2 + j];
        }
    }
    __syncthreads();
    if (w < 4) {                           // rows 0-63: full result
        const int hc = cta * 4 + q;
        float b2f  = 2.f * bias[hc];
        float b2i1 = 2.f * bias[HID + hc];
        float b2i2 = 2.f * bias[2 * HID + hc];
        float b2o  = 2.f * bias[3 * HID + hc];
#pragma unroll
        for (int rr = 0; rr < 2; rr++) {
            int row = row0 + rr * 8;
            const float* xr = xchg + row * 17;
            float gf = ff[0][rr * 2 + 0] + xr[0 * 4 + q] + b2f;
            float g1 = ff[1][rr * 2 + 0] + xr[1 * 4 + q] + b2i1;
            float g2 = ff[0][rr * 2 + 1] + xr[2 * 4 + q] + b2i2;
            float go = ff[1][rr * 2 + 1] + xr[3 * 4 + q] + b2o;
            float c = cst[row * HID + hc];
            c = sigf(gf) * c + sigf(g1) * tanhf(g2);
            cst[row * HID + hc] = c;
            float h = sigf(go) * tanhf(c);
            bf16 hi = __float2bfloat16(h);
            bf16 lo = __float2bfloat16(h - __bfloat162float(hi));
            hdst[row * HID + hc] = hi;
            hdst[(row + 64) * HID + hc] = lo;
            if (odst) odst[row * HID + hc] = h;
        }
    }
    __syncthreads();                       // xchg reuse safety (two epilogues back-to-back)
}

// ---- one-time per replay: split x into bf16 hi/lo stacked rows ----
__global__ void pack_x(const float* __restrict__ x) {
    size_t i = (size_t)blockIdx.x * blockDim.x + threadIdx.x;
    if (i < (size_t)SLEN * BATCH * HID) {
        int kk = (int)(i % HID);
        size_t sr = i / HID;
        int r = (int)(sr % BATCH);
        int s = (int)(sr / BATCH);
        float v = x[i];
        bf16 hi = __float2bfloat16(v);
        gx[s][r][kk] = hi;
        gx[s][64 + r][kk] = __float2bfloat16(v - __bfloat162float(hi));
    }
}

// ---- one-time per replay: split + permute weights ----
__global__ void pack_w(const float* __restrict__ Wx0, const float* __restrict__ Wh0,
                       const float* __restrict__ Wx1, const float* __restrict__ Wh1) {
    size_t i = (size_t)blockIdx.x * blockDim.x + threadIdx.x;  // 2*128*32*1024
    if (i >= (size_t)2 * NCTA * 32 * 1024) return;
    int kk = (int)(i & 1023);
    size_t t = i >> 10;
    int n32 = (int)(t & 31); t >>= 5;
    int cta = (int)(t & 127);
    int layer = (int)(t >> 7);
    int n = n32 & 15;                      // real col index within CTA
    int g = (n & 1) * 2 + (n >> 3);        // gate permutation (thread-local gate sets)
    int q = (n >> 1) & 3;
    int col = g * HID + cta * 4 + q;
    const float* Wx = layer ? Wx1 : Wx0;
    const float* Wh = layer ? Wh1 : Wh0;
    float v = (kk < HID) ? Wx[kk * 2048 + col] : Wh[(kk - HID) * 2048 + col];
    bf16 hi = __float2bfloat16(v);
    g_wb[layer][cta][n32][kk] = (n32 < 16) ? hi
                              : __float2bfloat16(v - __bfloat162float(hi));
}

__global__ void init_kernel() {
    int idx = blockIdx.x * blockDim.x + threadIdx.x;
    if (idx < 2 * 128 * HID) {
        ((bf16*)gh0s)[idx] = __float2bfloat16(0.f);
        ((bf16*)gh1s)[idx] = __float2bfloat16(0.f);
    }
    if (idx < BATCH * HID) { g_c0[idx] = 0.f; g_c1[idx] = 0.f; }
}

// ---- skewed step, MERGED phases at full grid: launch k runs layer0(step k)
// and layer1(step k-1) in one interleaved chunk pipeline (independent inputs). ----
__global__ __launch_bounds__(NTHR, 1)
void step_kernel(const float* __restrict__ b0, const float* __restrict__ b1,
                 float* __restrict__ out, int k) {
    extern __shared__ char smem[];
    uint32_t sb = smem_u32(smem);
    float* xchg = (float*)(smem + SM_X);
    const int tid = threadIdx.x, w = tid >> 5, l = tid & 31;
    const int cta = blockIdx.x;
    const int p = k & 1, pq = p ^ 1;
    const bool doA = (k < SLEN), doB = (k > 0);

    float dA[16], dB[16];
#pragma unroll
    for (int j = 0; j < 16; j++) { dA[j] = 0.f; dB[j] = 0.f; }

    // chunk c: k-range [c*128, c*128+128); c<4 -> first source, c>=4 -> second
    auto stage_iter = [&](int c, int buf) {
        if (doA) {
            const bf16* aA = (c < 4) ? (&gx[k][0][0] + c * 128)
                                     : (&gh0s[p][0][0] + (c - 4) * 128);
            stageA(sb + SM_A0 + buf * A_BUF, aA, tid);
            stageB(sb + SM_B0 + buf * B_BUF, &g_wb[0][cta][0][0] + c * 128, tid);
        }
        if (doB) {
            const bf16* aB = (c < 4) ? (&gh0s[p][0][0] + c * 128)
                                     : (&gh1s[p][0][0] + (c - 4) * 128);
            stageA(sb + SM_A1 + buf * A_BUF, aB, tid);
            stageB(sb + SM_B1 + buf * B_BUF, &g_wb[1][cta][0][0] + c * 128, tid);
        }
        cp_commit();
    };

    stage_iter(0, 0);
#pragma unroll 1
    for (int c = 0; c < 8; c++) {
        if (c < 7) {
            stage_iter(c + 1, (c + 1) & 1);
            cp_wait1();                    // chunk c landed
        } else {
            cp_wait0();
        }
        __syncthreads();
        if (doA) mma_chunk(sb + SM_A0 + (c & 1) * A_BUF, sb + SM_B0 + (c & 1) * B_BUF, w, l, dA);
        if (doB) mma_chunk(sb + SM_A1 + (c & 1) * A_BUF, sb + SM_B1 + (c & 1) * B_BUF, w, l, dB);
        __syncthreads();
    }

    if (doA) epilogue(dA, xchg, b0, g_c0, &gh0s[pq][0][0], nullptr, cta, w, l);
    if (doB) epilogue(dB, xchg, b1, g_c1, &gh1s[pq][0][0],
                      out + (size_t)(k - 1) * BATCH * HID, cta, w, l);
}

extern "C" void kernel_launch(void* const* d_in, const int* in_sizes, int n_in,
                              void* d_out, int out_size) {
    const float* x   = (const float*)d_in[0];
    const float* Wx0 = (const float*)d_in[1];
    const float* Wh0 = (const float*)d_in[2];
    const float* b0  = (const float*)d_in[3];
    const float* Wx1 = (const float*)d_in[4];
    const float* Wh1 = (const float*)d_in[5];
    const float* b1  = (const float*)d_in[6];
    float* out = (float*)d_out;

    static int attr_done = 0;
    if (!attr_done) {
        cudaFuncSetAttribute(step_kernel,
                             cudaFuncAttributeMaxDynamicSharedMemorySize, SM_TOTAL);
        attr_done = 1;
    }

    pack_x<<<(SLEN * BATCH * HID + 255) / 256, 256>>>(x);
    pack_w<<<(int)((2ull * NCTA * 32 * 1024 + 255) / 256), 256>>>(Wx0, Wh0, Wx1, Wh1);
    init_kernel<<<(2 * 128 * HID + 255) / 256, 256>>>();
    for (int k = 0; k <= SLEN; k++) {
        step_kernel<<<NCTA, NTHR, SM_TOTAL>>>(b0, b1, out, k);
    }
}

// round 11
// speedup vs baseline: 1.6476x; 1.2083x over previous
#include <cuda_runtime.h>
#include <cuda_bf16.h>
#include <cooperative_groups.h>
#include <cstdint>

namespace cg = cooperative_groups;

#define SLEN  512
#define BATCH 64
#define HID   512
#define NCTA  128
#define NTHR  256
#define AB    272                   // A-tile smem pitch (bytes): conflict-free ldmatrix
#define WP    2064                  // W-tile smem pitch (2048 + 16)
#define A_BUF (128 * AB)            // 34816 per A chunk buffer
#define SM_W  0                     // 64 rows x WP = 132096 (both layers, persistent)
#define SM_A  (64 * WP)             // 2 x A_BUF
#define SM_X  (SM_A + 2 * A_BUF)    // xchg: 64 x 17 floats
#define SM_TOTAL (SM_X + 64 * 17 * 4)   // 206080 B

typedef __nv_bfloat16 bf16;

// ---- persistent device state (allocation-free rule) ----
__device__ __align__(128) bf16  gx[SLEN][128][HID];   // x split: rows 0-63 hi, 64-127 lo
__device__ __align__(128) bf16  gh0s[2][128][HID];    // h0 split, ping-pong
__device__ __align__(128) bf16  gh1s[2][128][HID];    // h1 split, ping-pong
// weights: [layer][cta][n'(32)][k(1024)]; n'<16 = hi, n'>=16 = lo of col(n'-16)
// col(n) = g*512 + cta*4 + q, with g = (n&1)*2 + (n>>3), q = (n>>1)&3
__device__ __align__(128) bf16  g_wb[2][NCTA][32][1024];

// ---------------- helpers ----------------
__device__ __forceinline__ uint32_t smem_u32(const void* p) {
    uint32_t a;
    asm("{ .reg .u64 t; cvta.to.shared.u64 t, %1; cvt.u32.u64 %0, t; }" : "=r"(a) : "l"(p));
    return a;
}
__device__ __forceinline__ void cpa16(uint32_t dst, const void* src) {
    asm volatile("cp.async.cg.shared.global [%0], [%1], 16;\n" :: "r"(dst), "l"(src));
}
__device__ __forceinline__ void cp_commit() { asm volatile("cp.async.commit_group;\n" ::: "memory"); }
__device__ __forceinline__ void cp_wait1()  { asm volatile("cp.async.wait_group 1;\n" ::: "memory"); }
__device__ __forceinline__ void cp_wait0()  { asm volatile("cp.async.wait_group 0;\n" ::: "memory"); }

__device__ __forceinline__ void ldsm4(uint32_t& r0, uint32_t& r1, uint32_t& r2, uint32_t& r3,
                                      uint32_t addr) {
    asm volatile("ldmatrix.sync.aligned.m8n8.x4.shared.b16 {%0,%1,%2,%3}, [%4];"
                 : "=r"(r0), "=r"(r1), "=r"(r2), "=r"(r3) : "r"(addr));
}
__device__ __forceinline__ void mma16816(float* d, const uint32_t* a, uint32_t b0, uint32_t b1) {
    asm volatile(
        "mma.sync.aligned.m16n8k16.row.col.f32.bf16.bf16.f32 "
        "{%0,%1,%2,%3}, {%4,%5,%6,%7}, {%8,%9}, {%0,%1,%2,%3};"
        : "+f"(d[0]), "+f"(d[1]), "+f"(d[2]), "+f"(d[3])
        : "r"(a[0]), "r"(a[1]), "r"(a[2]), "r"(a[3]), "r"(b0), "r"(b1));
}
__device__ __forceinline__ float sigf(float x) { return 1.0f / (1.0f + __expf(-x)); }

// ---- stage one A chunk (128 rows x 128 k) ----
__device__ __forceinline__ void stageA(uint32_t ab, const bf16* __restrict__ a, int tid) {
#pragma unroll
    for (int i = 0; i < 8; i++) {
        int u = i * NTHR + tid;            // 0..2047
        int row = u >> 4, cu = u & 15;
        cpa16(ab + row * AB + cu * 16, a + row * HID + cu * 8);
    }
}

// ---- one chunk-phase MMA: A from chunk buf, B from persistent W smem ----
// wBase already includes layer offset and chunk-k byte offset (ck*256).
__device__ __forceinline__ void mma_chunkW(uint32_t aBase, uint32_t wBase, int w, int l,
                                           float* __restrict__ d) {
    uint32_t sA  = aBase + (16 * w + (l & 15)) * AB + (l >> 4) * 16;
    uint32_t sB0 = wBase + (l & 15) * WP + (l >> 4) * 16;
    uint32_t sB1 = sB0 + 16 * WP;
#pragma unroll
    for (int j = 0; j < 8; j++) {          // 8 k-steps of 16
        uint32_t a[4], p0, p1, p2, p3, q0, q1, q2, q3;
        ldsm4(a[0], a[1], a[2], a[3], sA + j * 32);
        ldsm4(p0, p1, p2, p3, sB0 + j * 32);   // n' 0-15 (hi cols)
        ldsm4(q0, q1, q2, q3, sB1 + j * 32);   // n' 16-31 (lo cols)
        mma16816(d + 0,  a, p0, p2);
        mma16816(d + 4,  a, p1, p3);
        mma16816(d + 8,  a, q0, q2);
        mma16816(d + 12, a, q1, q3);
    }
}

// ---- epilogue: fold cols (n, n+16) locally, rows (r, r+64) via smem; c in regs ----
__device__ __forceinline__ void epilogue(const float* __restrict__ d, float* __restrict__ xchg,
                                         const float* __restrict__ bias, float* __restrict__ creg,
                                         bf16* __restrict__ hdst, float* __restrict__ odst,
                                         int cta, int w, int l) {
    float ff[2][4];
#pragma unroll
    for (int t = 0; t < 2; t++)
#pragma unroll
        for (int r = 0; r < 4; r++) ff[t][r] = d[t * 4 + r] + d[(t + 2) * 4 + r];

    const int q = l & 3;
    const int row0 = 16 * w + (l >> 2);
    if (w >= 4) {                          // rows 64-127 = lo partials -> xchg
#pragma unroll
        for (int rr = 0; rr < 2; rr++) {
            int row = row0 + rr * 8 - 64;
#pragma unroll
            for (int t = 0; t < 2; t++)
#pragma unroll
                for (int j = 0; j < 2; j++)
                    xchg[row * 17 + (j * 2 + t) * 4 + q] = ff[t][rr * 2 + j];
        }
    }
    __syncthreads();
    if (w < 4) {                           // rows 0-63: full result
        const int hc = cta * 4 + q;
        float b2f  = 2.f * bias[hc];
        float b2i1 = 2.f * bias[HID + hc];
        float b2i2 = 2.f * bias[2 * HID + hc];
        float b2o  = 2.f * bias[3 * HID + hc];
#pragma unroll
        for (int rr = 0; rr < 2; rr++) {
            int row = row0 + rr * 8;
            const float* xr = xchg + row * 17;
            float gf = ff[0][rr * 2 + 0] + xr[0 * 4 + q] + b2f;
            float g1 = ff[1][rr * 2 + 0] + xr[1 * 4 + q] + b2i1;
            float g2 = ff[0][rr * 2 + 1] + xr[2 * 4 + q] + b2i2;
            float go = ff[1][rr * 2 + 1] + xr[3 * 4 + q] + b2o;
            float c = creg[rr];
            c = sigf(gf) * c + sigf(g1) * tanhf(g2);
            creg[rr] = c;
            float h = sigf(go) * tanhf(c);
            bf16 hi = __float2bfloat16(h);
            bf16 lo = __float2bfloat16(h - __bfloat162float(hi));
            hdst[row * HID + hc] = hi;
            hdst[(row + 64) * HID + hc] = lo;
            if (odst) odst[row * HID + hc] = h;
        }
    }
    __syncthreads();                       // xchg reuse safety
}

// ---- one-time per replay: split x into bf16 hi/lo stacked rows ----
__global__ void pack_x(const float* __restrict__ x) {
    size_t i = (size_t)blockIdx.x * blockDim.x + threadIdx.x;
    if (i < (size_t)SLEN * BATCH * HID) {
        int kk = (int)(i % HID);
        size_t sr = i / HID;
        int r = (int)(sr % BATCH);
        int s = (int)(sr / BATCH);
        float v = x[i];
        bf16 hi = __float2bfloat16(v);
        gx[s][r][kk] = hi;
        gx[s][64 + r][kk] = __float2bfloat16(v - __bfloat162float(hi));
    }
}

// ---- one-time per replay: split + permute weights ----
__global__ void pack_w(const float* __restrict__ Wx0, const float* __restrict__ Wh0,
                       const float* __restrict__ Wx1, const float* __restrict__ Wh1) {
    size_t i = (size_t)blockIdx.x * blockDim.x + threadIdx.x;  // 2*128*32*1024
    if (i >= (size_t)2 * NCTA * 32 * 1024) return;
    int kk = (int)(i & 1023);
    size_t t = i >> 10;
    int n32 = (int)(t & 31); t >>= 5;
    int cta = (int)(t & 127);
    int layer = (int)(t >> 7);
    int n = n32 & 15;
    int g = (n & 1) * 2 + (n >> 3);
    int q = (n >> 1) & 3;
    int col = g * HID + cta * 4 + q;
    const float* Wx = layer ? Wx1 : Wx0;
    const float* Wh = layer ? Wh1 : Wh0;
    float v = (kk < HID) ? Wx[kk * 2048 + col] : Wh[(kk - HID) * 2048 + col];
    bf16 hi = __float2bfloat16(v);
    g_wb[layer][cta][n32][kk] = (n32 < 16) ? hi
                              : __float2bfloat16(v - __bfloat162float(hi));
}

// ---- persistent cooperative kernel: whole sequence in one launch ----
__global__ __launch_bounds__(NTHR, 1)
void lstm_persist(const float* __restrict__ b0, const float* __restrict__ b1,
                  float* __restrict__ out) {
    cg::grid_group grid = cg::this_grid();
    extern __shared__ char smem[];
    uint32_t sb = smem_u32(smem);
    float* xchg = (float*)(smem + SM_X);
    const int tid = threadIdx.x, w = tid >> 5, l = tid & 31;
    const int cta = blockIdx.x;

    // ---- prologue: load both layers' weights into persistent smem ----
#pragma unroll
    for (int i = 0; i < 32; i++) {
        int u = i * NTHR + tid;            // 0..8191
        int row = u >> 7, cu = u & 127;    // row 0..63, 128 x 16B per row
        const bf16* src = (row < 32) ? &g_wb[0][cta][row][0] : &g_wb[1][cta][row - 32][0];
        cpa16(sb + SM_W + row * WP + cu * 16, src + cu * 8);
    }
    cp_commit();

    // zero this CTA's h columns (both parities; cross-CTA reads need full zero init)
    {
        int hc = cta * 4 + (tid & 3);
        int row = tid >> 2;                // 0..63
        bf16 z = __float2bfloat16(0.f);
#pragma unroll
        for (int par = 0; par < 2; par++) {
            gh0s[par][row][hc] = z;  gh0s[par][row + 64][hc] = z;
            gh1s[par][row][hc] = z;  gh1s[par][row + 64][hc] = z;
        }
    }
    float cA[2] = {0.f, 0.f}, cB[2] = {0.f, 0.f};   // cell states live in registers
    cp_wait0();
    grid.sync();                           // weights + zeroed h visible everywhere

    // ---- main loop: iteration k does layer0(step k) + layer1(step k-1) ----
#pragma unroll 1
    for (int k = 0; k <= SLEN; k++) {
        const int p = k & 1, pq = p ^ 1;
        const bool doA = (k < SLEN), doB = (k > 0);
        const int cstart = doA ? 0 : 4;    // chunks: 0-3 x, 4-7 h0, 8-11 h1
        const int cend   = doB ? 12 : 8;

        float dA[16], dB[16];
#pragma unroll
        for (int j = 0; j < 16; j++) { dA[j] = 0.f; dB[j] = 0.f; }

        auto chunk_src = [&](int c) -> const bf16* {
            if (c < 4)  return &gx[k][0][0]    + c * 128;
            if (c < 8)  return &gh0s[p][0][0]  + (c - 4) * 128;
            return              &gh1s[p][0][0] + (c - 8) * 128;
        };

        stageA(sb + SM_A, chunk_src(cstart), tid);
        cp_commit();
#pragma unroll 1
        for (int c = cstart; c < cend; c++) {
            int buf = (c - cstart) & 1;
            if (c + 1 < cend) {
                stageA(sb + SM_A + (buf ^ 1) * A_BUF, chunk_src(c + 1), tid);
                cp_commit();
                cp_wait1();
            } else {
                cp_wait0();
            }
            __syncthreads();
            uint32_t aB = sb + SM_A + buf * A_BUF;
            if (c < 8 && doA)              // phase A: W0, k-offset c*128 -> c*256 bytes
                mma_chunkW(aB, sb + SM_W + c * 256, w, l, dA);
            if (c >= 4 && doB)             // phase B: W1, k-offset (c-4)*128
                mma_chunkW(aB, sb + SM_W + 32 * WP + (c - 4) * 256, w, l, dB);
            __syncthreads();
        }

        if (doA) epilogue(dA, xchg, b0, cA, &gh0s[pq][0][0], nullptr, cta, w, l);
        if (doB) epilogue(dB, xchg, b1, cB, &gh1s[pq][0][0],
                          out + (size_t)(k - 1) * BATCH * HID, cta, w, l);
        grid.sync();                       // h[pq] visible before next iteration
    }
}

extern "C" void kernel_launch(void* const* d_in, const int* in_sizes, int n_in,
                              void* d_out, int out_size) {
    const float* x   = (const float*)d_in[0];
    const float* Wx0 = (const float*)d_in[1];
    const float* Wh0 = (const float*)d_in[2];
    const float* b0  = (const float*)d_in[3];
    const float* Wx1 = (const float*)d_in[4];
    const float* Wh1 = (const float*)d_in[5];
    const float* b1  = (const float*)d_in[6];
    float* out = (float*)d_out;

    static int attr_done = 0;
    if (!attr_done) {
        cudaFuncSetAttribute(lstm_persist,
                             cudaFuncAttributeMaxDynamicSharedMemorySize, SM_TOTAL);
        attr_done = 1;
    }

    pack_x<<<(SLEN * BATCH * HID + 255) / 256, 256>>>(x);
    pack_w<<<(int)((2ull * NCTA * 32 * 1024 + 255) / 256), 256>>>(Wx0, Wh0, Wx1, Wh1);

    void* args[] = {(void*)&b0, (void*)&b1, (void*)&out};
    cudaLaunchCooperativeKernel((const void*)lstm_persist, dim3(NCTA), dim3(NTHR),
                                args, SM_TOTAL, (cudaStream_t)0);
}

// round 12
// speedup vs baseline: 1.7124x; 1.0393x over previous
#include <cuda_runtime.h>
#include <cuda_bf16.h>
#include <cooperative_groups.h>
#include <cstdint>

namespace cg = cooperative_groups;

#define SLEN  512
#define BATCH 64
#define HID   512
#define NCTA  128
#define NTHR  256
#define WP    2064                  // W smem pitch (2048 + 16): conflict-free ldmatrix
#define AB    144                   // A-chunk pitch (128 + 16), 64-k chunks
#define A_BUF (128 * AB)            // 18432 per ring slot
#define SM_W  0                     // 64 rows x WP = 132096 (both layers, persistent)
#define SM_A  (64 * WP)             // ring: 4 x A_BUF
#define SM_TOTAL (SM_A + 4 * A_BUF) // 205824 B

typedef __nv_bfloat16 bf16;

// ---- persistent device state (allocation-free rule) ----
__device__ __align__(128) bf16  gx[SLEN][128][HID];   // x split: rows 0-63 hi, 64-127 lo
__device__ __align__(128) bf16  gh0s[2][128][HID];    // h0 split, ping-pong
__device__ __align__(128) bf16  gh1s[2][128][HID];    // h1 split, ping-pong
// weights: [layer][cta][n'(32)][k(1024)]; n'<16 = hi, n'>=16 = lo of col(n'-16)
// col(n) = g*512 + cta*4 + q, with g = (n&1)*2 + (n>>3), q = (n>>1)&3
__device__ __align__(128) bf16  g_wb[2][NCTA][32][1024];

// ---------------- helpers ----------------
__device__ __forceinline__ uint32_t smem_u32(const void* p) {
    uint32_t a;
    asm("{ .reg .u64 t; cvta.to.shared.u64 t, %1; cvt.u32.u64 %0, t; }" : "=r"(a) : "l"(p));
    return a;
}
__device__ __forceinline__ void cpa16(uint32_t dst, const void* src) {
    asm volatile("cp.async.cg.shared.global [%0], [%1], 16;\n" :: "r"(dst), "l"(src));
}
__device__ __forceinline__ void cp_commit() { asm volatile("cp.async.commit_group;\n" ::: "memory"); }
__device__ __forceinline__ void cp_wait2()  { asm volatile("cp.async.wait_group 2;\n" ::: "memory"); }
__device__ __forceinline__ void cp_wait0()  { asm volatile("cp.async.wait_group 0;\n" ::: "memory"); }

__device__ __forceinline__ void ldsm4(uint32_t& r0, uint32_t& r1, uint32_t& r2, uint32_t& r3,
                                      uint32_t addr) {
    asm volatile("ldmatrix.sync.aligned.m8n8.x4.shared.b16 {%0,%1,%2,%3}, [%4];"
                 : "=r"(r0), "=r"(r1), "=r"(r2), "=r"(r3) : "r"(addr));
}
__device__ __forceinline__ void mma16816(float* d, const uint32_t* a, uint32_t b0, uint32_t b1) {
    asm volatile(
        "mma.sync.aligned.m16n8k16.row.col.f32.bf16.bf16.f32 "
        "{%0,%1,%2,%3}, {%4,%5,%6,%7}, {%8,%9}, {%0,%1,%2,%3};"
        : "+f"(d[0]), "+f"(d[1]), "+f"(d[2]), "+f"(d[3])
        : "r"(a[0]), "r"(a[1]), "r"(a[2]), "r"(a[3]), "r"(b0), "r"(b1));
}
__device__ __forceinline__ float sigf(float x) { return 1.0f / (1.0f + __expf(-x)); }

// ---- stage one 64-k A chunk (128 tile rows), warp-interleaved hi/lo rows ----
// tile row dr: warp w = dr>>4, i = dr&15; global row = (i<8) ? 8w+i : 64 + 8w + (i-8)
__device__ __forceinline__ void stageA(uint32_t ab, const bf16* __restrict__ src, int tid) {
#pragma unroll
    for (int i = 0; i < 4; i++) {
        int u = i * NTHR + tid;            // 0..1023
        int dr = u >> 3, cu = u & 7;       // dest row, 16B unit within 128B row
        int sr = ((dr & 8) ? 64 : 0) + ((dr >> 4) << 3) + (dr & 7);
        cpa16(ab + dr * AB + cu * 16, src + sr * HID + cu * 8);
    }
}

// ---- one chunk-phase MMA: A from ring slot, B from persistent W smem ----
__device__ __forceinline__ void mma_chunkW(uint32_t aBase, uint32_t wBase, int w, int l,
                                           float* __restrict__ d) {
    uint32_t sA  = aBase + (16 * w + (l & 15)) * AB + (l >> 4) * 16;
    uint32_t sB0 = wBase + (l & 15) * WP + (l >> 4) * 16;
    uint32_t sB1 = sB0 + 16 * WP;
#pragma unroll
    for (int j = 0; j < 4; j++) {          // 4 k-steps of 16
        uint32_t a[4], p0, p1, p2, p3, q0, q1, q2, q3;
        ldsm4(a[0], a[1], a[2], a[3], sA + j * 32);
        ldsm4(p0, p1, p2, p3, sB0 + j * 32);   // n' 0-15 (hi cols)
        ldsm4(q0, q1, q2, q3, sB1 + j * 32);   // n' 16-31 (lo cols)
        mma16816(d + 0,  a, p0, p2);
        mma16816(d + 4,  a, p1, p3);
        mma16816(d + 8,  a, q0, q2);
        mma16816(d + 12, a, q1, q3);
    }
}

// ---- thread-local epilogue: row-fold (c0+c2) and col-fold (tile t + t+2) in regs ----
__device__ __forceinline__ void epilogue(const float* __restrict__ d,
                                         const float* __restrict__ bias4, float& cstate,
                                         bf16* __restrict__ hdst, float* __restrict__ odst,
                                         int R, int hc) {
    // G[t][jj]: gate value for col n = 8t + 2q + jj -> gate g = jj*2 + t
    float gf  = d[0] + d[2] + d[8]  + d[10] + bias4[0];   // t0 jj0 -> f
    float gi1 = d[4] + d[6] + d[12] + d[14] + bias4[1];   // t1 jj0 -> i1
    float gi2 = d[1] + d[3] + d[9]  + d[11] + bias4[2];   // t0 jj1 -> i2
    float go  = d[5] + d[7] + d[13] + d[15] + bias4[3];   // t1 jj1 -> o
    float c = cstate;
    c = sigf(gf) * c + sigf(gi1) * tanhf(gi2);
    cstate = c;
    float h = sigf(go) * tanhf(c);
    bf16 hi = __float2bfloat16(h);
    bf16 lo = __float2bfloat16(h - __bfloat162float(hi));
    hdst[R * HID + hc] = hi;
    hdst[(R + 64) * HID + hc] = lo;
    if (odst) odst[R * HID + hc] = h;
}

// ---- one-time per replay: split x into bf16 hi/lo stacked rows ----
__global__ void pack_x(const float* __restrict__ x) {
    size_t i = (size_t)blockIdx.x * blockDim.x + threadIdx.x;
    if (i < (size_t)SLEN * BATCH * HID) {
        int kk = (int)(i % HID);
        size_t sr = i / HID;
        int r = (int)(sr % BATCH);
        int s = (int)(sr / BATCH);
        float v = x[i];
        bf16 hi = __float2bfloat16(v);
        gx[s][r][kk] = hi;
        gx[s][64 + r][kk] = __float2bfloat16(v - __bfloat162float(hi));
    }
}

// ---- one-time per replay: split + permute weights ----
__global__ void pack_w(const float* __restrict__ Wx0, const float* __restrict__ Wh0,
                       const float* __restrict__ Wx1, const float* __restrict__ Wh1) {
    size_t i = (size_t)blockIdx.x * blockDim.x + threadIdx.x;  // 2*128*32*1024
    if (i >= (size_t)2 * NCTA * 32 * 1024) return;
    int kk = (int)(i & 1023);
    size_t t = i >> 10;
    int n32 = (int)(t & 31); t >>= 5;
    int cta = (int)(t & 127);
    int layer = (int)(t >> 7);
    int n = n32 & 15;
    int g = (n & 1) * 2 + (n >> 3);
    int q = (n >> 1) & 3;
    int col = g * HID + cta * 4 + q;
    const float* Wx = layer ? Wx1 : Wx0;
    const float* Wh = layer ? Wh1 : Wh0;
    float v = (kk < HID) ? Wx[kk * 2048 + col] : Wh[(kk - HID) * 2048 + col];
    bf16 hi = __float2bfloat16(v);
    g_wb[layer][cta][n32][kk] = (n32 < 16) ? hi
                              : __float2bfloat16(v - __bfloat162float(hi));
}

// ---- persistent cooperative kernel ----
__global__ __launch_bounds__(NTHR, 1)
void lstm_persist(const float* __restrict__ b0, const float* __restrict__ b1,
                  float* __restrict__ out) {
    cg::grid_group grid = cg::this_grid();
    extern __shared__ char smem[];
    uint32_t sb = smem_u32(smem);
    const int tid = threadIdx.x, w = tid >> 5, l = tid & 31;
    const int cta = blockIdx.x;
    const int R  = 8 * w + (l >> 2);       // this thread's batch row
    const int hc = cta * 4 + (l & 3);      // this thread's h-column

    // ---- prologue: both layers' weights -> persistent smem ----
#pragma unroll
    for (int i = 0; i < 32; i++) {
        int u = i * NTHR + tid;            // 0..8191
        int row = u >> 7, cu = u & 127;
        const bf16* src = (row < 32) ? &g_wb[0][cta][row][0] : &g_wb[1][cta][row - 32][0];
        cpa16(sb + SM_W + row * WP + cu * 16, src + cu * 8);
    }
    cp_commit();

    // zero this CTA's h columns (both parities)
    {
        int zc = cta * 4 + (tid & 3);
        int zr = tid >> 2;                 // 0..63
        bf16 z = __float2bfloat16(0.f);
#pragma unroll
        for (int par = 0; par < 2; par++) {
            gh0s[par][zr][zc] = z;  gh0s[par][zr + 64][zc] = z;
            gh1s[par][zr][zc] = z;  gh1s[par][zr + 64][zc] = z;
        }
    }
    float bA[4], bB[4];
#pragma unroll
    for (int g = 0; g < 4; g++) { bA[g] = 2.f * b0[g * HID + hc]; bB[g] = 2.f * b1[g * HID + hc]; }
    float cA = 0.f, cB = 0.f;

    cp_wait0();
    __syncthreads();                       // weights visible CTA-wide

    // prefetch iteration-0 x chunks 0..2 (slots 0..2); grid.sync shadows their latency
#pragma unroll
    for (int t = 0; t < 3; t++) {
        stageA(sb + SM_A + t * A_BUF, &gx[0][0][0] + t * 64, tid);
        cp_commit();
    }
    grid.sync();

    // ---- main loop: iteration k = layer0(step k) + layer1(step k-1) ----
    // chunk universe: 0-7 x[k], 8-15 h0[p] (feeds BOTH phases), 16-23 h1[p]
#pragma unroll 1
    for (int k = 0; k <= SLEN; k++) {
        const int p = k & 1, pq = p ^ 1;
        const bool doA = (k < SLEN), doB = (k > 0);
        const int cstart = doA ? 0 : 8;
        const int cend   = doB ? 24 : 16;

        if (k == SLEN) {                   // no prefetch happened for this iteration
#pragma unroll
            for (int t = 0; t < 3; t++) {  // chunks 8,9,10 -> slots 0,1,2
                stageA(sb + SM_A + t * A_BUF, &gh0s[p][0][0] + t * 64, tid);
                cp_commit();
            }
        }

        float dA[16], dB[16];
#pragma unroll
        for (int j = 0; j < 16; j++) { dA[j] = 0.f; dB[j] = 0.f; }

#pragma unroll 1
        for (int c = cstart; c < cend; c++) {
            cp_wait2();                    // chunk c landed (2 newer groups may pend)
            __syncthreads();               // visible + slot (c+3)&3 free
            if (c + 3 < cend) {
                int cn = c + 3;
                const bf16* src = (cn < 8)  ? (&gx[k][0][0]    + cn * 64)
                                 : (cn < 16) ? (&gh0s[p][0][0] + (cn - 8) * 64)
                                            : (&gh1s[p][0][0] + (cn - 16) * 64);
                stageA(sb + SM_A + (cn & 3) * A_BUF, src, tid);
            }
            cp_commit();                   // one group per chunk (empty near tail)
            uint32_t aB = sb + SM_A + (c & 3) * A_BUF;
            if (doA && c < 16)
                mma_chunkW(aB, sb + SM_W + c * 128, w, l, dA);
            if (doB && c >= 8)
                mma_chunkW(aB, sb + SM_W + 32 * WP + (c - 8) * 128, w, l, dB);
        }

        // thread-local epilogues (no barriers, no smem)
        if (doA) epilogue(dA, bA, cA, &gh0s[pq][0][0], nullptr, R, hc);
        if (doB) epilogue(dB, bB, cB, &gh1s[pq][0][0],
                          out + (size_t)(k - 1) * BATCH * HID, R, hc);

        // prefetch next iteration's x chunks before the sync (constant data;
        // slots 0,1,2 safe: their last readers finished before chunk-23 barrier)
        if (k + 1 < SLEN) {
#pragma unroll
            for (int t = 0; t < 3; t++) {
                stageA(sb + SM_A + t * A_BUF, &gx[k + 1][0][0] + t * 64, tid);
                cp_commit();
            }
        }
        grid.sync();
    }
}

extern "C" void kernel_launch(void* const* d_in, const int* in_sizes, int n_in,
                              void* d_out, int out_size) {
    const float* x   = (const float*)d_in[0];
    const float* Wx0 = (const float*)d_in[1];
    const float* Wh0 = (const float*)d_in[2];
    const float* b0  = (const float*)d_in[3];
    const float* Wx1 = (const float*)d_in[4];
    const float* Wh1 = (const float*)d_in[5];
    const float* b1  = (const float*)d_in[6];
    float* out = (float*)d_out;

    static int attr_done = 0;
    if (!attr_done) {
        cudaFuncSetAttribute(lstm_persist,
                             cudaFuncAttributeMaxDynamicSharedMemorySize, SM_TOTAL);
        attr_done = 1;
    }

    pack_x<<<(SLEN * BATCH * HID + 255) / 256, 256>>>(x);
    pack_w<<<(int)((2ull * NCTA * 32 * 1024 + 255) / 256), 256>>>(Wx0, Wh0, Wx1, Wh1);

    void* args[] = {(void*)&b0, (void*)&b1, (void*)&out};
    cudaLaunchCooperativeKernel((const void*)lstm_persist, dim3(NCTA), dim3(NTHR),
                                args, SM_TOTAL, (cudaStream_t)0);
}

// round 13
// speedup vs baseline: 2.0446x; 1.1940x over previous
#include <cuda_runtime.h>
#include <cuda_bf16.h>
#include <cooperative_groups.h>
#include <cstdint>

namespace cg = cooperative_groups;

#define SLEN  512
#define BATCH 64
#define HID   512
#define NCTA  128
#define NTHR  256
// smem: W = 64 rows x 2048B (XOR-swizzled, no pad), A ring = 3 x (128 rows x 256B)
#define SM_W   0
#define W_ROW  2048
#define SM_A   131072
#define A_SLOT 32768
#define A_ROW  256
#define SM_TOTAL (SM_A + 3 * A_SLOT)   // 229376 B = 224 KB

typedef __nv_bfloat16 bf16;

// ---- persistent device state (allocation-free rule) ----
__device__ __align__(128) bf16 gx[SLEN][128][HID];    // x split: rows 0-63 hi, 64-127 lo
__device__ __align__(128) bf16 gh0s[2][128][HID];     // h0 split, ping-pong
__device__ __align__(128) bf16 gh1s[2][128][HID];     // h1 split, ping-pong
// weights: [layer][cta][n'(32)][k(1024)]; n'<16 = hi, n'>=16 = lo of col(n'-16)
// col(n) = g*512 + cta*4 + q, with g = (n&1)*2 + (n>>3), q = (n>>1)&3
__device__ __align__(128) bf16 g_wb[2][NCTA][32][1024];

// ---------------- helpers ----------------
__device__ __forceinline__ uint32_t smem_u32(const void* p) {
    uint32_t a;
    asm("{ .reg .u64 t; cvta.to.shared.u64 t, %1; cvt.u32.u64 %0, t; }" : "=r"(a) : "l"(p));
    return a;
}
__device__ __forceinline__ void cpa16(uint32_t dst, const void* src) {
    asm volatile("cp.async.cg.shared.global [%0], [%1], 16;\n" :: "r"(dst), "l"(src));
}
__device__ __forceinline__ void cp_commit() { asm volatile("cp.async.commit_group;\n" ::: "memory"); }
__device__ __forceinline__ void cp_wait1()  { asm volatile("cp.async.wait_group 1;\n" ::: "memory"); }
__device__ __forceinline__ void cp_wait0()  { asm volatile("cp.async.wait_group 0;\n" ::: "memory"); }

__device__ __forceinline__ void ldsm4(uint32_t& r0, uint32_t& r1, uint32_t& r2, uint32_t& r3,
                                      uint32_t addr) {
    asm volatile("ldmatrix.sync.aligned.m8n8.x4.shared.b16 {%0,%1,%2,%3}, [%4];"
                 : "=r"(r0), "=r"(r1), "=r"(r2), "=r"(r3) : "r"(addr));
}
__device__ __forceinline__ void mma16816(float* d, const uint32_t* a, uint32_t b0, uint32_t b1) {
    asm volatile(
        "mma.sync.aligned.m16n8k16.row.col.f32.bf16.bf16.f32 "
        "{%0,%1,%2,%3}, {%4,%5,%6,%7}, {%8,%9}, {%0,%1,%2,%3};"
        : "+f"(d[0]), "+f"(d[1]), "+f"(d[2]), "+f"(d[3])
        : "r"(a[0]), "r"(a[1]), "r"(a[2]), "r"(a[3]), "r"(b0), "r"(b1));
}
__device__ __forceinline__ float sigf(float x) { return 1.0f / (1.0f + __expf(-x)); }

// ---- stage one 128-k A chunk (128 tile rows x 16 swizzled 16B units) ----
// tile row dr: warp = dr>>4, i = dr&15; global row = (i<8) ? 8*warp+i : 64+8*warp+(i-8)
__device__ __forceinline__ void stageA(uint32_t ab, const bf16* __restrict__ src, int tid) {
#pragma unroll
    for (int i = 0; i < 8; i++) {
        int u = i * NTHR + tid;            // 0..2047
        int dr = u >> 4, cu = u & 15;
        int sr = ((dr & 8) ? 64 : 0) + ((dr >> 4) << 3) + (dr & 7);
        cpa16(ab + dr * A_ROW + ((cu ^ (dr & 7)) << 4), src + sr * HID + cu * 8);
    }
}

// ---- one 128-k chunk: shared A-ldsm feeds up to both phases ----
__device__ __forceinline__ void mma_chunk(uint32_t sb, uint32_t aBase, int koA, int koB,
                                          bool pA, bool pB, int w, int l,
                                          float* __restrict__ dA, float* __restrict__ dB) {
    const int rA = 16 * w + (l & 15);
    const uint32_t aRow = aBase + rA * A_ROW;
    const int axor = rA & 7;
    const int rb = l & 15;
    const int bxor = rb & 7;
    const int hi = l >> 4;
#pragma unroll
    for (int j = 0; j < 8; j++) {          // 8 k-steps of 16
        int ua = 2 * j + hi;
        uint32_t a[4];
        ldsm4(a[0], a[1], a[2], a[3], aRow + ((ua ^ axor) << 4));
        if (pA) {
            int u = koA + (ua ^ bxor);
            uint32_t p0, p1, p2, p3, q0, q1, q2, q3;
            ldsm4(p0, p1, p2, p3, sb + SM_W + rb * W_ROW + (u << 4));          // L0 hi
            ldsm4(q0, q1, q2, q3, sb + SM_W + (rb + 16) * W_ROW + (u << 4));   // L0 lo
            mma16816(dA + 0,  a, p0, p2);
            mma16816(dA + 4,  a, p1, p3);
            mma16816(dA + 8,  a, q0, q2);
            mma16816(dA + 12, a, q1, q3);
        }
        if (pB) {
            int u = koB + (ua ^ bxor);
            uint32_t p0, p1, p2, p3, q0, q1, q2, q3;
            ldsm4(p0, p1, p2, p3, sb + SM_W + (rb + 32) * W_ROW + (u << 4));   // L1 hi
            ldsm4(q0, q1, q2, q3, sb + SM_W + (rb + 48) * W_ROW + (u << 4));   // L1 lo
            mma16816(dB + 0,  a, p0, p2);
            mma16816(dB + 4,  a, p1, p3);
            mma16816(dB + 8,  a, q0, q2);
            mma16816(dB + 12, a, q1, q3);
        }
    }
}

// ---- thread-local epilogue: row-fold (c0+c2) and col-fold (t, t+2) in registers ----
__device__ __forceinline__ void epilogue(const float* __restrict__ d,
                                         const float* __restrict__ bias4, float& cstate,
                                         bf16* __restrict__ hdst, float* __restrict__ odst,
                                         int R, int hc) {
    float gf  = d[0] + d[2] + d[8]  + d[10] + bias4[0];
    float gi1 = d[4] + d[6] + d[12] + d[14] + bias4[1];
    float gi2 = d[1] + d[3] + d[9]  + d[11] + bias4[2];
    float go  = d[5] + d[7] + d[13] + d[15] + bias4[3];
    float c = cstate;
    c = sigf(gf) * c + sigf(gi1) * tanhf(gi2);
    cstate = c;
    float h = sigf(go) * tanhf(c);
    bf16 hi = __float2bfloat16(h);
    bf16 lo = __float2bfloat16(h - __bfloat162float(hi));
    hdst[R * HID + hc] = hi;
    hdst[(R + 64) * HID + hc] = lo;
    if (odst) odst[R * HID + hc] = h;
}

// ---- one-time per replay: FUSED pack (x split + weight split/permute) ----
// Fusing keeps per-replay launch count at 2 so ncu (-s 5) lands on lstm_persist.
__global__ void pack_all(const float* __restrict__ x,
                         const float* __restrict__ Wx0, const float* __restrict__ Wh0,
                         const float* __restrict__ Wx1, const float* __restrict__ Wh1) {
    size_t i = (size_t)blockIdx.x * blockDim.x + threadIdx.x;
    if (i < (size_t)SLEN * BATCH * HID) {
        int kk = (int)(i % HID);
        size_t sr = i / HID;
        int r = (int)(sr % BATCH);
        int s = (int)(sr / BATCH);
        float v = x[i];
        bf16 hi = __float2bfloat16(v);
        gx[s][r][kk] = hi;
        gx[s][64 + r][kk] = __float2bfloat16(v - __bfloat162float(hi));
    }
    if (i < (size_t)2 * NCTA * 32 * 1024) {
        int kk = (int)(i & 1023);
        size_t t = i >> 10;
        int n32 = (int)(t & 31); t >>= 5;
        int cta = (int)(t & 127);
        int layer = (int)(t >> 7);
        int n = n32 & 15;
        int g = (n & 1) * 2 + (n >> 3);
        int q = (n >> 1) & 3;
        int col = g * HID + cta * 4 + q;
        const float* Wx = layer ? Wx1 : Wx0;
        const float* Wh = layer ? Wh1 : Wh0;
        float v = (kk < HID) ? Wx[kk * 2048 + col] : Wh[(kk - HID) * 2048 + col];
        bf16 hi = __float2bfloat16(v);
        g_wb[layer][cta][n32][kk] = (n32 < 16) ? hi
                                  : __float2bfloat16(v - __bfloat162float(hi));
    }
}

// ---- persistent cooperative kernel ----
__global__ __launch_bounds__(NTHR, 1)
void lstm_persist(const float* __restrict__ b0, const float* __restrict__ b1,
                  float* __restrict__ out) {
    cg::grid_group grid = cg::this_grid();
    extern __shared__ char smem[];
    uint32_t sb = smem_u32(smem);
    const int tid = threadIdx.x, w = tid >> 5, l = tid & 31;
    const int cta = blockIdx.x;
    const int R  = 8 * w + (l >> 2);       // this thread's batch row
    const int hc = cta * 4 + (l & 3);      // this thread's h-column

    // ---- prologue: both layers' weights -> persistent swizzled smem ----
#pragma unroll
    for (int i = 0; i < 32; i++) {
        int u = i * NTHR + tid;            // 0..8191 16B units
        int row = u >> 7, cu = u & 127;
        const bf16* src = (row < 32) ? &g_wb[0][cta][row][0] : &g_wb[1][cta][row - 32][0];
        cpa16(sb + SM_W + row * W_ROW + ((cu ^ (row & 7)) << 4), src + cu * 8);
    }
    cp_commit();

    // zero this CTA's h columns (both parities)
    {
        int zc = cta * 4 + (tid & 3);
        int zr = tid >> 2;                 // 0..63
        bf16 z = __float2bfloat16(0.f);
#pragma unroll
        for (int par = 0; par < 2; par++) {
            gh0s[par][zr][zc] = z;  gh0s[par][zr + 64][zc] = z;
            gh1s[par][zr][zc] = z;  gh1s[par][zr + 64][zc] = z;
        }
    }
    float bA[4], bB[4];
#pragma unroll
    for (int g = 0; g < 4; g++) { bA[g] = 2.f * b0[g * HID + hc]; bB[g] = 2.f * b1[g * HID + hc]; }
    float cA = 0.f, cB = 0.f;

    cp_wait0();
    __syncthreads();                       // weights visible CTA-wide

    // prefetch iteration-0 x chunks 0,1 (slots 0,1); grid.sync shadows latency
    stageA(sb + SM_A + 0 * A_SLOT, &gx[0][0][0] + 0 * 128, tid); cp_commit();
    stageA(sb + SM_A + 1 * A_SLOT, &gx[0][0][0] + 1 * 128, tid); cp_commit();
    grid.sync();

    // ---- main loop: iteration k = layer0(step k) + layer1(step k-1) ----
    // chunk universe (128-k each): 0-3 x[k], 4-7 h0[p] (feeds BOTH phases), 8-11 h1[p]
#pragma unroll 1
    for (int k = 0; k <= SLEN; k++) {
        const int p = k & 1, pq = p ^ 1;
        const bool doA = (k < SLEN), doB = (k > 0);
        const int cstart = doA ? 0 : 4;
        const int cend   = doB ? 12 : 8;

        if (k == SLEN) {                   // h0 wasn't prefetchable (written last iter)
            stageA(sb + SM_A + 1 * A_SLOT, &gh0s[p][0][0] + 0 * 128, tid); cp_commit();
            stageA(sb + SM_A + 2 * A_SLOT, &gh0s[p][0][0] + 1 * 128, tid); cp_commit();
        }

        float dA[16], dB[16];
#pragma unroll
        for (int j = 0; j < 16; j++) { dA[j] = 0.f; dB[j] = 0.f; }

#pragma unroll 1
        for (int c = cstart; c < cend; c++) {
            cp_wait1();                    // chunk c landed (c+1 may pend)
            __syncthreads();               // visible + slot (c+2)%3 free
            if (c + 2 < cend) {
                int cn = c + 2;
                const bf16* src = (cn < 4) ? (&gx[k][0][0]    + cn * 128)
                                 : (cn < 8) ? (&gh0s[p][0][0] + (cn - 4) * 128)
                                            : (&gh1s[p][0][0] + (cn - 8) * 128);
                stageA(sb + SM_A + (cn % 3) * A_SLOT, src, tid);
            }
            cp_commit();                   // one group per chunk (empty near tail)
            mma_chunk(sb, sb + SM_A + (c % 3) * A_SLOT, c * 16, (c - 4) * 16,
                      doA && (c < 8), doB && (c >= 4), w, l, dA, dB);
        }
        __syncthreads();                   // all chunk reads done before slot reuse

        if (doA) epilogue(dA, bA, cA, &gh0s[pq][0][0], nullptr, R, hc);
        if (doB) epilogue(dB, bB, cB, &gh1s[pq][0][0],
                          out + (size_t)(k - 1) * BATCH * HID, R, hc);

        if (k + 1 < SLEN) {                // prefetch next iteration's x (constant data)
            stageA(sb + SM_A + 0 * A_SLOT, &gx[k + 1][0][0] + 0 * 128, tid); cp_commit();
            stageA(sb + SM_A + 1 * A_SLOT, &gx[k + 1][0][0] + 1 * 128, tid); cp_commit();
        }
        grid.sync();                       // h[pq] visible grid-wide
    }
}

extern "C" void kernel_launch(void* const* d_in, const int* in_sizes, int n_in,
                              void* d_out, int out_size) {
    const float* x   = (const float*)d_in[0];
    const float* Wx0 = (const float*)d_in[1];
    const float* Wh0 = (const float*)d_in[2];
    const float* b0  = (const float*)d_in[3];
    const float* Wx1 = (const float*)d_in[4];
    const float* Wh1 = (const float*)d_in[5];
    const float* b1  = (const float*)d_in[6];
    float* out = (float*)d_out;

    static int attr_done = 0;
    if (!attr_done) {
        cudaFuncSetAttribute(lstm_persist,
                             cudaFuncAttributeMaxDynamicSharedMemorySize, SM_TOTAL);
        attr_done = 1;
    }

    pack_all<<<(int)(((size_t)SLEN * BATCH * HID + 255) / 256), 256>>>(x, Wx0, Wh0, Wx1, Wh1);

    void* args[] = {(void*)&b0, (void*)&b1, (void*)&out};
    cudaLaunchCooperativeKernel((const void*)lstm_persist, dim3(NCTA), dim3(NTHR),
                                args, SM_TOTAL, (cudaStream_t)0);
}

// round 14
// speedup vs baseline: 2.3545x; 1.1516x over previous
#include <cuda_runtime.h>
#include <cuda_bf16.h>
#include <cooperative_groups.h>
#include <cstdint>

namespace cg = cooperative_groups;

#define SLEN  512
#define BATCH 64
#define HID   512
#define NCTA  128
#define NTHR  256
// smem: W = 64 rows x 2048B (XOR-swizzled), A ring = 3 x (128 rows x 256B)
#define SM_W   0
#define W_ROW  2048
#define SM_A   131072
#define A_SLOT 32768
#define A_ROW  256
#define SM_TOTAL (SM_A + 3 * A_SLOT)   // 229376 B

typedef __nv_bfloat16 bf16;

// ---- persistent device state (allocation-free rule) ----
__device__ __align__(128) bf16 gx[SLEN][128][HID];    // x split: rows 0-63 hi, 64-127 lo
__device__ __align__(128) bf16 gh0s[2][128][HID];     // h0 split, ping-pong
__device__ __align__(128) bf16 gh1s[2][128][HID];     // h1 split, ping-pong
// weights: [layer][cta][n32][k]; n32 = cg*16 + part*8 + m, part 0=hi 1=lo,
// real col idx = 8*cg + m -> gate = idx>>2, hq = idx&3, col = gate*512 + cta*4 + hq
__device__ __align__(128) bf16 g_wb[2][NCTA][32][1024];

// ---------------- helpers ----------------
__device__ __forceinline__ uint32_t smem_u32(const void* p) {
    uint32_t a;
    asm("{ .reg .u64 t; cvta.to.shared.u64 t, %1; cvt.u32.u64 %0, t; }" : "=r"(a) : "l"(p));
    return a;
}
__device__ __forceinline__ void cpa16(uint32_t dst, const void* src) {
    asm volatile("cp.async.cg.shared.global [%0], [%1], 16;\n" :: "r"(dst), "l"(src));
}
__device__ __forceinline__ void cp_commit() { asm volatile("cp.async.commit_group;\n" ::: "memory"); }
__device__ __forceinline__ void cp_wait1()  { asm volatile("cp.async.wait_group 1;\n" ::: "memory"); }
__device__ __forceinline__ void cp_wait0()  { asm volatile("cp.async.wait_group 0;\n" ::: "memory"); }

__device__ __forceinline__ void ldsm4(uint32_t& r0, uint32_t& r1, uint32_t& r2, uint32_t& r3,
                                      uint32_t addr) {
    asm volatile("ldmatrix.sync.aligned.m8n8.x4.shared.b16 {%0,%1,%2,%3}, [%4];"
                 : "=r"(r0), "=r"(r1), "=r"(r2), "=r"(r3) : "r"(addr));
}
__device__ __forceinline__ void mma16816(float* d, const uint32_t* a, uint32_t b0, uint32_t b1) {
    asm volatile(
        "mma.sync.aligned.m16n8k16.row.col.f32.bf16.bf16.f32 "
        "{%0,%1,%2,%3}, {%4,%5,%6,%7}, {%8,%9}, {%0,%1,%2,%3};"
        : "+f"(d[0]), "+f"(d[1]), "+f"(d[2]), "+f"(d[3])
        : "r"(a[0]), "r"(a[1]), "r"(a[2]), "r"(a[3]), "r"(b0), "r"(b1));
}
__device__ __forceinline__ float sigf(float x) { return 1.0f / (1.0f + __expf(-x)); }

// ---- stage one 128-k A chunk; tile row dr: rg = dr>>5 owns real rows 16rg..16rg+15,
// i = dr&31: i<16 -> hi of real row 16rg+i, i>=16 -> lo of real row 16rg+(i-16) ----
__device__ __forceinline__ void stageA(uint32_t ab, const bf16* __restrict__ src, int tid) {
#pragma unroll
    for (int i = 0; i < 8; i++) {
        int u = i * NTHR + tid;            // 0..2047
        int dr = u >> 4, cu = u & 15;
        int ii = dr & 31;
        int sr = ((ii & 16) ? 64 : 0) + ((dr >> 5) << 4) + (ii & 15);
        cpa16(ab + dr * A_ROW + ((cu ^ (dr & 7)) << 4), src + sr * HID + cu * 8);
    }
}

// ---- one 128-k chunk: warp (rg, cg) = 16 real rows x 8 real cols/phase.
// 3-term MMA per phase (hi*hi, hi*lo, lo*hi; lo*lo dropped ~2^-16). ----
__device__ __forceinline__ void mma_chunk(uint32_t sb, uint32_t aBase, int koA, int koB,
                                          bool pA, bool pB, int rg, int cgx, int l,
                                          float* __restrict__ dA, float* __restrict__ dB) {
    const int rh = 32 * rg + (l & 15);     // hi-row tile row
    const uint32_t aRowH = aBase + rh * A_ROW;
    const uint32_t aRowL = aRowH + 16 * A_ROW;
    const int ax = (l & 15) & 7;           // same xor for hi and lo rows
    const int rb = l & 15;
    const int bxor = rb & 7;
    const int hi = l >> 4;
    const uint32_t wA = sb + SM_W + (cgx * 16 + rb) * W_ROW;        // layer0
    const uint32_t wB = wA + 32 * W_ROW;                            // layer1
#pragma unroll
    for (int j = 0; j < 8; j++) {          // 8 k-steps of 16
        int ua = 2 * j + hi;
        uint32_t ah[4], al[4];
        ldsm4(ah[0], ah[1], ah[2], ah[3], aRowH + ((ua ^ ax) << 4));
        ldsm4(al[0], al[1], al[2], al[3], aRowL + ((ua ^ ax) << 4));
        int u = (ua ^ bxor) << 4;
        if (pA) {
            uint32_t b0, b1, b2, b3;
            ldsm4(b0, b1, b2, b3, wA + ((koA << 4) + u));   // rows: 0-7 hi cols, 8-15 lo
            mma16816(dA + 0, ah, b0, b2);  // hi rows x hi cols
            mma16816(dA + 4, ah, b1, b3);  // hi rows x lo cols
            mma16816(dA + 8, al, b0, b2);  // lo rows x hi cols
        }
        if (pB) {
            uint32_t b0, b1, b2, b3;
            ldsm4(b0, b1, b2, b3, wB + ((koB << 4) + u));
            mma16816(dB + 0, ah, b0, b2);
            mma16816(dB + 4, ah, b1, b3);
            mma16816(dB + 8, al, b0, b2);
        }
    }
}

// ---- gate write: fold 3 terms in regs, scatter full gate values to xbuf ----
__device__ __forceinline__ void gate_write(const float* __restrict__ d,
                                           float* __restrict__ xbuf,
                                           int rg, int cgx, int l) {
    float v0 = d[0] + d[4] + d[8];
    float v1 = d[1] + d[5] + d[9];
    float v2 = d[2] + d[6] + d[10];
    float v3 = d[3] + d[7] + d[11];
    int r0 = 16 * rg + (l >> 2);
    int c0 = 8 * cgx + 2 * (l & 3);
    xbuf[r0 * 17 + c0]           = v0;
    xbuf[r0 * 17 + c0 + 1]       = v1;
    xbuf[(r0 + 8) * 17 + c0]     = v2;
    xbuf[(r0 + 8) * 17 + c0 + 1] = v3;
}

// ---- cell update from xbuf: reader thread owns (row = tid>>2, hq = tid&3) ----
__device__ __forceinline__ void cell_update(const float* __restrict__ xbuf,
                                            const float* __restrict__ bias4, float& cstate,
                                            bf16* __restrict__ hdst, float* __restrict__ odst,
                                            int row, int hq, int hc) {
    float gf  = xbuf[row * 17 + 0 + hq]  + bias4[0];
    float gi1 = xbuf[row * 17 + 4 + hq]  + bias4[1];
    float gi2 = xbuf[row * 17 + 8 + hq]  + bias4[2];
    float go  = xbuf[row * 17 + 12 + hq] + bias4[3];
    float c = cstate;
    c = sigf(gf) * c + sigf(gi1) * tanhf(gi2);
    cstate = c;
    float h = sigf(go) * tanhf(c);
    bf16 hi = __float2bfloat16(h);
    bf16 lo = __float2bfloat16(h - __bfloat162float(hi));
    hdst[row * HID + hc] = hi;
    hdst[(row + 64) * HID + hc] = lo;
    if (odst) odst[row * HID + hc] = h;
}

// ---- one-time per replay: FUSED pack (x split + weight split/permute) ----
__global__ void pack_all(const float* __restrict__ x,
                         const float* __restrict__ Wx0, const float* __restrict__ Wh0,
                         const float* __restrict__ Wx1, const float* __restrict__ Wh1) {
    size_t i = (size_t)blockIdx.x * blockDim.x + threadIdx.x;
    if (i < (size_t)SLEN * BATCH * HID) {
        int kk = (int)(i % HID);
        size_t sr = i / HID;
        int r = (int)(sr % BATCH);
        int s = (int)(sr / BATCH);
        float v = x[i];
        bf16 hi = __float2bfloat16(v);
        gx[s][r][kk] = hi;
        gx[s][64 + r][kk] = __float2bfloat16(v - __bfloat162float(hi));
    }
    if (i < (size_t)2 * NCTA * 32 * 1024) {
        int kk = (int)(i & 1023);
        size_t t = i >> 10;
        int n32 = (int)(t & 31); t >>= 5;
        int cta = (int)(t & 127);
        int layer = (int)(t >> 7);
        int cgx = n32 >> 4;
        int part = (n32 >> 3) & 1;         // 0 = hi, 1 = lo
        int m = n32 & 7;
        int idx = 8 * cgx + m;
        int g = idx >> 2, hq = idx & 3;
        int col = g * HID + cta * 4 + hq;
        const float* Wx = layer ? Wx1 : Wx0;
        const float* Wh = layer ? Wh1 : Wh0;
        float v = (kk < HID) ? Wx[kk * 2048 + col] : Wh[(kk - HID) * 2048 + col];
        bf16 hi = __float2bfloat16(v);
        g_wb[layer][cta][n32][kk] = (part == 0) ? hi
                                  : __float2bfloat16(v - __bfloat162float(hi));
    }
}

// ---- persistent cooperative kernel ----
__global__ __launch_bounds__(NTHR, 1)
void lstm_persist(const float* __restrict__ b0, const float* __restrict__ b1,
                  float* __restrict__ out) {
    cg::grid_group grid = cg::this_grid();
    extern __shared__ char smem[];
    uint32_t sb = smem_u32(smem);
    const int tid = threadIdx.x, w = tid >> 5, l = tid & 31;
    const int rg = w >> 1, cgx = w & 1;    // 4 row-groups x 2 col-groups
    const int cta = blockIdx.x;
    const int rowR = tid >> 2;             // reader row (0..63)
    const int hq   = tid & 3;              // reader h-col within CTA
    const int hc   = cta * 4 + hq;

    float* xA = (float*)(smem + SM_A + 2 * A_SLOT);        // gate xchg (slot-2 reuse)
    float* xB = xA + 2048;                                  // +8KB

    // ---- prologue: both layers' weights -> persistent swizzled smem ----
#pragma unroll
    for (int i = 0; i < 32; i++) {
        int u = i * NTHR + tid;            // 0..8191 16B units
        int row = u >> 7, cu = u & 127;
        const bf16* src = (row < 32) ? &g_wb[0][cta][row][0] : &g_wb[1][cta][row - 32][0];
        cpa16(sb + SM_W + row * W_ROW + ((cu ^ (row & 7)) << 4), src + cu * 8);
    }
    cp_commit();

    // zero this CTA's h columns (both parities)
    {
        bf16 z = __float2bfloat16(0.f);
#pragma unroll
        for (int par = 0; par < 2; par++) {
            gh0s[par][rowR][hc] = z;  gh0s[par][rowR + 64][hc] = z;
            gh1s[par][rowR][hc] = z;  gh1s[par][rowR + 64][hc] = z;
        }
    }
    float bA[4], bB[4];
#pragma unroll
    for (int g = 0; g < 4; g++) { bA[g] = 2.f * b0[g * HID + hc]; bB[g] = 2.f * b1[g * HID + hc]; }
    float cA = 0.f, cB = 0.f;              // cell states on reader identity

    cp_wait0();
    __syncthreads();

    // prefetch iteration-0 x chunks 0,1 (slots 0,1); grid.sync shadows latency
    stageA(sb + SM_A + 0 * A_SLOT, &gx[0][0][0] + 0 * 128, tid); cp_commit();
    stageA(sb + SM_A + 1 * A_SLOT, &gx[0][0][0] + 1 * 128, tid); cp_commit();
    grid.sync();

    // ---- main loop: iteration k = layer0(step k) + layer1(step k-1) ----
    // chunks (128-k): 0-3 x[k], 4-7 h0[p] (feeds BOTH phases), 8-11 h1[p]
#pragma unroll 1
    for (int k = 0; k <= SLEN; k++) {
        const int p = k & 1, pq = p ^ 1;
        const bool doA = (k < SLEN), doB = (k > 0);
        const int cstart = doA ? 0 : 4;
        const int cend   = doB ? 12 : 8;

        if (k == SLEN) {                   // h0 wasn't prefetchable (written last iter)
            stageA(sb + SM_A + 1 * A_SLOT, &gh0s[p][0][0] + 0 * 128, tid); cp_commit();
            stageA(sb + SM_A + 2 * A_SLOT, &gh0s[p][0][0] + 1 * 128, tid); cp_commit();
        }

        float dA[12], dB[12];
#pragma unroll
        for (int j = 0; j < 12; j++) { dA[j] = 0.f; dB[j] = 0.f; }

#pragma unroll 1
        for (int c = cstart; c < cend; c++) {
            cp_wait1();                    // chunk c landed (c+1 may pend)
            __syncthreads();               // visible + slot (c+2)%3 free
            if (c + 2 < cend) {
                int cn = c + 2;
                const bf16* src = (cn < 4) ? (&gx[k][0][0]    + cn * 128)
                                 : (cn < 8) ? (&gh0s[p][0][0] + (cn - 4) * 128)
                                            : (&gh1s[p][0][0] + (cn - 8) * 128);
                stageA(sb + SM_A + (cn % 3) * A_SLOT, src, tid);
            }
            cp_commit();                   // one group per chunk (empty near tail)
            mma_chunk(sb, sb + SM_A + (c % 3) * A_SLOT, c * 16, (c - 4) * 16,
                      doA && (c < 8), doB && (c >= 4), rg, cgx, l, dA, dB);
        }
        __syncthreads();                   // slot-2 chunk reads done -> xchg may use it

        // gate exchange + cell update (xbufs live in A-slot 2, free until next restage)
        if (doA) gate_write(dA, xA, rg, cgx, l);
        if (doB) gate_write(dB, xB, rg, cgx, l);
        __syncthreads();
        if (doA) cell_update(xA, bA, cA, &gh0s[pq][0][0], nullptr, rowR, hq, hc);
        if (doB) cell_update(xB, bB, cB, &gh1s[pq][0][0],
                             out + (size_t)(k - 1) * BATCH * HID, rowR, hq, hc);

        if (k + 1 < SLEN) {                // prefetch next iteration's x (constant data)
            stageA(sb + SM_A + 0 * A_SLOT, &gx[k + 1][0][0] + 0 * 128, tid); cp_commit();
            stageA(sb + SM_A + 1 * A_SLOT, &gx[k + 1][0][0] + 1 * 128, tid); cp_commit();
        }
        grid.sync();                       // h[pq] + epilogue reads ordered grid-wide
    }
}

extern "C" void kernel_launch(void* const* d_in, const int* in_sizes, int n_in,
                              void* d_out, int out_size) {
    const float* x   = (const float*)d_in[0];
    const float* Wx0 = (const float*)d_in[1];
    const float* Wh0 = (const float*)d_in[2];
    const float* b0  = (const float*)d_in[3];
    const float* Wx1 = (const float*)d_in[4];
    const float* Wh1 = (const float*)d_in[5];
    const float* b1  = (const float*)d_in[6];
    float* out = (float*)d_out;

    static int attr_done = 0;
    if (!attr_done) {
        cudaFuncSetAttribute(lstm_persist,
                             cudaFuncAttributeMaxDynamicSharedMemorySize, SM_TOTAL);
        attr_done = 1;
    }

    pack_all<<<(int)(((size_t)SLEN * BATCH * HID + 255) / 256), 256>>>(x, Wx0, Wh0, Wx1, Wh1);

    void* args[] = {(void*)&b0, (void*)&b1, (void*)&out};
    cudaLaunchCooperativeKernel((const void*)lstm_persist, dim3(NCTA), dim3(NTHR),
                                args, SM_TOTAL, (cudaStream_t)0);
}

// round 17
// speedup vs baseline: 2.4854x; 1.0556x over previous
#include <cuda_runtime.h>
#include <cuda_bf16.h>
#include <cooperative_groups.h>
#include <cstdint>

namespace cg = cooperative_groups;

#define SLEN  512
#define BATCH 64
#define HID   512
#define NCTA  128
#define NTHR  256
// main smem: W = 64 rows x 2048B (XOR-swizzled), A ring = 3 x (128 rows x 256B)
#define SM_W   0
#define W_ROW  2048
#define SM_A   131072
#define A_SLOT 32768
#define A_ROW  256
#define SM_TOTAL (SM_A + 3 * A_SLOT)   // 229376 B
// prex smem: x resident 128 rows x 1024B, W ring 2 x (32 rows x 1024B)
#define PX_X   0
#define PX_W   131072
#define PX_TOTAL (131072 + 2 * 32768)  // 196608 B

typedef __nv_bfloat16 bf16;

// ---- persistent device state (allocation-free rule) ----
__device__ __align__(128) bf16 gx[SLEN][128][HID];    // x split: rows 0-63 hi, 64-127 lo
__device__ __align__(128) bf16 gh0s[2][128][HID];     // h0 split, ping-pong
__device__ __align__(128) bf16 gh1s[2][128][HID];     // h1 split, ping-pong
// weights: [layer][cta][n32][k]; n32 = cg*16 + part*8 + m (part 0=hi 1=lo)
__device__ __align__(128) bf16 g_wb[2][NCTA][32][1024];
// precomputed x @ Wx0 partial gates, per-thread fragment layout
__device__ __align__(128) float4 g_xp[SLEN * NCTA * 256];

// ---------------- helpers ----------------
__device__ __forceinline__ uint32_t smem_u32(const void* p) {
    uint32_t a;
    asm("{ .reg .u64 t; cvta.to.shared.u64 t, %1; cvt.u32.u64 %0, t; }" : "=r"(a) : "l"(p));
    return a;
}
__device__ __forceinline__ void cpa16(uint32_t dst, const void* src) {
    asm volatile("cp.async.cg.shared.global [%0], [%1], 16;\n" :: "r"(dst), "l"(src));
}
__device__ __forceinline__ void cp_commit() { asm volatile("cp.async.commit_group;\n" ::: "memory"); }
__device__ __forceinline__ void cp_wait1()  { asm volatile("cp.async.wait_group 1;\n" ::: "memory"); }
__device__ __forceinline__ void cp_wait0()  { asm volatile("cp.async.wait_group 0;\n" ::: "memory"); }

__device__ __forceinline__ void ldsm4(uint32_t& r0, uint32_t& r1, uint32_t& r2, uint32_t& r3,
                                      uint32_t addr) {
    asm volatile("ldmatrix.sync.aligned.m8n8.x4.shared.b16 {%0,%1,%2,%3}, [%4];"
                 : "=r"(r0), "=r"(r1), "=r"(r2), "=r"(r3) : "r"(addr));
}
__device__ __forceinline__ void mma16816(float* d, const uint32_t* a, uint32_t b0, uint32_t b1) {
    asm volatile(
        "mma.sync.aligned.m16n8k16.row.col.f32.bf16.bf16.f32 "
        "{%0,%1,%2,%3}, {%4,%5,%6,%7}, {%8,%9}, {%0,%1,%2,%3};"
        : "+f"(d[0]), "+f"(d[1]), "+f"(d[2]), "+f"(d[3])
        : "r"(a[0]), "r"(a[1]), "r"(a[2]), "r"(a[3]), "r"(b0), "r"(b1));
}
__device__ __forceinline__ float sigf(float x) { return 1.0f / (1.0f + __expf(-x)); }

// ---- stage one 128-k A chunk (main); tile row dr: rg = dr>>5 owns 16 real rows,
// i = dr&31: i<16 -> hi of real row, i>=16 -> lo ----
__device__ __forceinline__ void stageA(uint32_t ab, const bf16* __restrict__ src, int tid) {
#pragma unroll
    for (int i = 0; i < 8; i++) {
        int u = i * NTHR + tid;            // 0..2047
        int dr = u >> 4, cu = u & 15;
        int ii = dr & 31;
        int sr = ((ii & 16) ? 64 : 0) + ((dr >> 5) << 4) + (ii & 15);
        cpa16(ab + dr * A_ROW + ((cu ^ (dr & 7)) << 4), src + sr * HID + cu * 8);
    }
}

// ---- one 128-k chunk (main): warp (rg, cg) = 16 rows x 8 cols/phase, 3-term ----
__device__ __forceinline__ void mma_chunk(uint32_t sb, uint32_t aBase, int koA, int koB,
                                          bool pA, bool pB, int rg, int cgx, int l,
                                          float* __restrict__ dA, float* __restrict__ dB) {
    const int rh = 32 * rg + (l & 15);
    const uint32_t aRowH = aBase + rh * A_ROW;
    const uint32_t aRowL = aRowH + 16 * A_ROW;
    const int ax = (l & 15) & 7;
    const int rb = l & 15;
    const int bxor = rb & 7;
    const int hi = l >> 4;
    const uint32_t wA = sb + SM_W + (cgx * 16 + rb) * W_ROW;        // layer0
    const uint32_t wB = wA + 32 * W_ROW;                            // layer1
#pragma unroll
    for (int j = 0; j < 8; j++) {
        int ua = 2 * j + hi;
        uint32_t ah[4], al[4];
        ldsm4(ah[0], ah[1], ah[2], ah[3], aRowH + ((ua ^ ax) << 4));
        ldsm4(al[0], al[1], al[2], al[3], aRowL + ((ua ^ ax) << 4));
        int u = (ua ^ bxor) << 4;
        if (pA) {
            uint32_t b0, b1, b2, b3;
            ldsm4(b0, b1, b2, b3, wA + ((koA << 4) + u));
            mma16816(dA + 0, ah, b0, b2);
            mma16816(dA + 4, ah, b1, b3);
            mma16816(dA + 8, al, b0, b2);
        }
        if (pB) {
            uint32_t b0, b1, b2, b3;
            ldsm4(b0, b1, b2, b3, wB + ((koB << 4) + u));
            mma16816(dB + 0, ah, b0, b2);
            mma16816(dB + 4, ah, b1, b3);
            mma16816(dB + 8, al, b0, b2);
        }
    }
}

// ---- gate write: fold 3 terms (+ precomputed x part), scatter to xbuf ----
__device__ __forceinline__ void gate_write(const float* __restrict__ d, const float4 px,
                                           float* __restrict__ xbuf,
                                           int rg, int cgx, int l) {
    float v0 = d[0] + d[4] + d[8]  + px.x;
    float v1 = d[1] + d[5] + d[9]  + px.y;
    float v2 = d[2] + d[6] + d[10] + px.z;
    float v3 = d[3] + d[7] + d[11] + px.w;
    int r0 = 16 * rg + (l >> 2);
    int c0 = 8 * cgx + 2 * (l & 3);
    xbuf[r0 * 17 + c0]           = v0;
    xbuf[r0 * 17 + c0 + 1]       = v1;
    xbuf[(r0 + 8) * 17 + c0]     = v2;
    xbuf[(r0 + 8) * 17 + c0 + 1] = v3;
}

// ---- cell update from xbuf: reader owns (row = tid>>2, hq = tid&3) ----
__device__ __forceinline__ void cell_update(const float* __restrict__ xbuf,
                                            const float* __restrict__ bias4, float& cstate,
                                            bf16* __restrict__ hdst, float* __restrict__ odst,
                                            int row, int hq, int hc) {
    float gf  = xbuf[row * 17 + 0 + hq]  + bias4[0];
    float gi1 = xbuf[row * 17 + 4 + hq]  + bias4[1];
    float gi2 = xbuf[row * 17 + 8 + hq]  + bias4[2];
    float go  = xbuf[row * 17 + 12 + hq] + bias4[3];
    float c = cstate;
    c = sigf(gf) * c + sigf(gi1) * tanhf(gi2);
    cstate = c;
    float h = sigf(go) * tanhf(c);
    bf16 hi = __float2bfloat16(h);
    bf16 lo = __float2bfloat16(h - __bfloat162float(hi));
    hdst[row * HID + hc] = hi;
    hdst[(row + 64) * HID + hc] = lo;
    if (odst) odst[row * HID + hc] = h;
}

// ---- one-time per replay: FUSED pack (x split + weight split/permute) ----
__global__ void pack_all(const float* __restrict__ x,
                         const float* __restrict__ Wx0, const float* __restrict__ Wh0,
                         const float* __restrict__ Wx1, const float* __restrict__ Wh1) {
    size_t i = (size_t)blockIdx.x * blockDim.x + threadIdx.x;
    if (i < (size_t)SLEN * BATCH * HID) {
        int kk = (int)(i % HID);
        size_t sr = i / HID;
        int r = (int)(sr % BATCH);
        int s = (int)(sr / BATCH);
        float v = x[i];
        bf16 hi = __float2bfloat16(v);
        gx[s][r][kk] = hi;
        gx[s][64 + r][kk] = __float2bfloat16(v - __bfloat162float(hi));
    }
    if (i < (size_t)2 * NCTA * 32 * 1024) {
        int kk = (int)(i & 1023);
        size_t t = i >> 10;
        int n32 = (int)(t & 31); t >>= 5;
        int cta = (int)(t & 127);
        int layer = (int)(t >> 7);
        int cgx = n32 >> 4;
        int part = (n32 >> 3) & 1;
        int m = n32 & 7;
        int idx = 8 * cgx + m;
        int g = idx >> 2, hq = idx & 3;
        int col = g * HID + cta * 4 + hq;
        const float* Wx = layer ? Wx1 : Wx0;
        const float* Wh = layer ? Wh1 : Wh0;
        float v = (kk < HID) ? Wx[kk * 2048 + col] : Wh[(kk - HID) * 2048 + col];
        bf16 hi = __float2bfloat16(v);
        g_wb[layer][cta][n32][kk] = (part == 0) ? hi
                                  : __float2bfloat16(v - __bfloat162float(hi));
    }
}

// ---- precompute x @ Wx0 for all steps (only k<512 of each W row = Wx part) ----
// grid: 128 blocks x 4 steps each. x[s] resident in smem; weights rung through.
// Pipeline discipline: prefetch-commit BEFORE compute, wait0 AFTER -> no group math.
__global__ __launch_bounds__(NTHR, 1)
void lstm_prex() {
    extern __shared__ char smem[];
    uint32_t sb = smem_u32(smem);
    const int tid = threadIdx.x, w = tid >> 5, l = tid & 31;
    const int rg = w >> 1, cgx = w & 1;
    const int sg = blockIdx.x;

    const int rh = 32 * rg + (l & 15);
    const uint32_t aH = sb + PX_X + rh * 1024;
    const uint32_t aL = aH + 16 * 1024;
    const int ax = (l & 15) & 7;
    const int rb = l & 15;
    const int bx = rb & 7;
    const int hi = l >> 4;

#pragma unroll 1
    for (int sl = 0; sl < 4; sl++) {
        const int s = sg * 4 + sl;
        // stage x[s]: 128 rows x 64 units (1024B rows), interleaved hi/lo, swizzled
#pragma unroll
        for (int i = 0; i < 32; i++) {
            int u = i * NTHR + tid;        // 0..8191
            int dr = u >> 6, cu = u & 63;
            int ii = dr & 31;
            int sr = ((ii & 16) ? 64 : 0) + ((dr >> 5) << 4) + (ii & 15);
            cpa16(sb + PX_X + dr * 1024 + ((cu ^ (dr & 7)) << 4),
                  &gx[s][0][0] + sr * HID + cu * 8);
        }
        // stage W[cta=0] (first 1024B of each row = Wx part) into slot 0
#pragma unroll
        for (int i = 0; i < 8; i++) {
            int u = i * NTHR + tid;        // 0..2047
            int row = u >> 6, cu = u & 63;
            cpa16(sb + PX_W + row * 1024 + ((cu ^ (row & 7)) << 4),
                  &g_wb[0][0][row][0] + cu * 8);
        }
        cp_commit();
        cp_wait0();                        // x + W0 fully landed (fixes R16 NaN)
        __syncthreads();

#pragma unroll 1
        for (int cta = 0; cta < NCTA; cta++) {
            // prefetch W[cta+1] into the other slot (its last reader was fenced
            // by the end-of-iteration barrier of cta-1)
            if (cta + 1 < NCTA) {
                uint32_t wd = sb + PX_W + ((cta + 1) & 1) * 32768;
#pragma unroll
                for (int i = 0; i < 8; i++) {
                    int u = i * NTHR + tid;
                    int row = u >> 6, cu = u & 63;
                    cpa16(wd + row * 1024 + ((cu ^ (row & 7)) << 4),
                          &g_wb[0][cta + 1][row][0] + cu * 8);
                }
                cp_commit();
            }

            float d[12];
#pragma unroll
            for (int j = 0; j < 12; j++) d[j] = 0.f;
            const uint32_t wb = sb + PX_W + (cta & 1) * 32768 + (cgx * 16 + rb) * 1024;
#pragma unroll 1
            for (int c = 0; c < 4; c++) {
#pragma unroll
                for (int j = 0; j < 8; j++) {
                    int ua = c * 16 + 2 * j + hi;
                    uint32_t ah[4], al[4], b0, b1, b2, b3;
                    ldsm4(ah[0], ah[1], ah[2], ah[3], aH + ((ua ^ ax) << 4));
                    ldsm4(al[0], al[1], al[2], al[3], aL + ((ua ^ ax) << 4));
                    ldsm4(b0, b1, b2, b3, wb + ((ua ^ bx) << 4));
                    mma16816(d + 0, ah, b0, b2);
                    mma16816(d + 4, ah, b1, b3);
                    mma16816(d + 8, al, b0, b2);
                }
            }
            g_xp[((size_t)s * NCTA + cta) * 256 + tid] =
                make_float4(d[0] + d[4] + d[8],  d[1] + d[5] + d[9],
                            d[2] + d[6] + d[10], d[3] + d[7] + d[11]);

            if (cta + 1 < NCTA) {
                cp_wait0();                // W[cta+1] landed (overlapped with compute)
                __syncthreads();           // + all warps done with slot cta&1
            }
        }
        __syncthreads();                   // x reads done before restage
    }
}

// ---- persistent cooperative kernel (recurrent part only) ----
__global__ __launch_bounds__(NTHR, 1)
void lstm_persist(const float* __restrict__ b0, const float* __restrict__ b1,
                  float* __restrict__ out) {
    cg::grid_group grid = cg::this_grid();
    extern __shared__ char smem[];
    uint32_t sb = smem_u32(smem);
    const int tid = threadIdx.x, w = tid >> 5, l = tid & 31;
    const int rg = w >> 1, cgx = w & 1;
    const int cta = blockIdx.x;
    const int rowR = tid >> 2;
    const int hq   = tid & 3;
    const int hc   = cta * 4 + hq;

    float* xA = (float*)(smem + SM_A + 2 * A_SLOT);   // gate xchg (slot-2 reuse)
    float* xB = xA + 2048;

    // ---- prologue: both layers' weights -> persistent swizzled smem ----
#pragma unroll
    for (int i = 0; i < 32; i++) {
        int u = i * NTHR + tid;
        int row = u >> 7, cu = u & 127;
        const bf16* src = (row < 32) ? &g_wb[0][cta][row][0] : &g_wb[1][cta][row - 32][0];
        cpa16(sb + SM_W + row * W_ROW + ((cu ^ (row & 7)) << 4), src + cu * 8);
    }
    cp_commit();
    {
        bf16 z = __float2bfloat16(0.f);
#pragma unroll
        for (int par = 0; par < 2; par++) {
            gh0s[par][rowR][hc] = z;  gh0s[par][rowR + 64][hc] = z;
            gh1s[par][rowR][hc] = z;  gh1s[par][rowR + 64][hc] = z;
        }
    }
    float bA[4], bB[4];
#pragma unroll
    for (int g = 0; g < 4; g++) { bA[g] = 2.f * b0[g * HID + hc]; bB[g] = 2.f * b1[g * HID + hc]; }
    float cA = 0.f, cB = 0.f;

    cp_wait0();
    __syncthreads();                       // weights visible CTA-wide
    grid.sync();                           // zeroed h visible grid-wide

    // ---- main loop: iteration k = layer0(step k) + layer1(step k-1) ----
    // chunks (128-k): 4-7 h0[p] (feeds BOTH phases), 8-11 h1[p]; x-part precomputed
#pragma unroll 1
    for (int k = 0; k <= SLEN; k++) {
        const int p = k & 1, pq = p ^ 1;
        const bool doA = (k < SLEN), doB = (k > 0);
        const int cend = doB ? 12 : 8;

        float4 px = doA ? g_xp[((size_t)k * NCTA + cta) * 256 + tid]
                        : make_float4(0.f, 0.f, 0.f, 0.f);

        float dA[12], dB[12];
#pragma unroll
        for (int j = 0; j < 12; j++) { dA[j] = 0.f; dB[j] = 0.f; }

        // stage first two h chunks (slots (4%3)=1, (5%3)=2): TWO groups precede wait1
        stageA(sb + SM_A + 1 * A_SLOT, &gh0s[p][0][0] + 0 * 128, tid); cp_commit();
        stageA(sb + SM_A + 2 * A_SLOT, &gh0s[p][0][0] + 1 * 128, tid); cp_commit();
#pragma unroll 1
        for (int c = 4; c < cend; c++) {
            if (c + 1 < cend) cp_wait1(); else cp_wait0();
            __syncthreads();               // chunk c visible + prior mma done
            if (c + 2 < cend) {
                int cn = c + 2;
                const bf16* src = (cn < 8) ? (&gh0s[p][0][0] + (cn - 4) * 128)
                                           : (&gh1s[p][0][0] + (cn - 8) * 128);
                stageA(sb + SM_A + (cn % 3) * A_SLOT, src, tid);
            }
            cp_commit();
            mma_chunk(sb, sb + SM_A + (c % 3) * A_SLOT, c * 16, (c - 4) * 16,
                      doA && (c < 8), doB, rg, cgx, l, dA, dB);
        }
        __syncthreads();                   // all slot reads done -> xchg may use slot 2

        if (doA) gate_write(dA, px, xA, rg, cgx, l);
        if (doB) gate_write(dB, make_float4(0.f, 0.f, 0.f, 0.f), xB, rg, cgx, l);
        __syncthreads();
        if (doA) cell_update(xA, bA, cA, &gh0s[pq][0][0], nullptr, rowR, hq, hc);
        if (doB) cell_update(xB, bB, cB, &gh1s[pq][0][0],
                             out + (size_t)(k - 1) * BATCH * HID, rowR, hq, hc);

        grid.sync();                       // h[pq] + epilogue reads ordered grid-wide
    }
}

extern "C" void kernel_launch(void* const* d_in, const int* in_sizes, int n_in,
                              void* d_out, int out_size) {
    const float* x   = (const float*)d_in[0];
    const float* Wx0 = (const float*)d_in[1];
    const float* Wh0 = (const float*)d_in[2];
    const float* b0  = (const float*)d_in[3];
    const float* Wx1 = (const float*)d_in[4];
    const float* Wh1 = (const float*)d_in[5];
    const float* b1  = (const float*)d_in[6];
    float* out = (float*)d_out;

    static int attr_done = 0;
    if (!attr_done) {
        cudaFuncSetAttribute(lstm_persist,
                             cudaFuncAttributeMaxDynamicSharedMemorySize, SM_TOTAL);
        cudaFuncSetAttribute(lstm_prex,
                             cudaFuncAttributeMaxDynamicSharedMemorySize, PX_TOTAL);
        attr_done = 1;
    }

    pack_all<<<(int)(((size_t)SLEN * BATCH * HID + 255) / 256), 256>>>(x, Wx0, Wh0, Wx1, Wh1);
    lstm_prex<<<NCTA, NTHR, PX_TOTAL>>>();

    void* args[] = {(void*)&b0, (void*)&b1, (void*)&out};
    cudaLaunchCooperativeKernel((const void*)lstm_persist, dim3(NCTA), dim3(NTHR),
                                args, SM_TOTAL, (cudaStream_t)0);
}